// round 1
// baseline (speedup 1.0000x reference)
#include <cuda_runtime.h>
#include <math.h>

// Problem constants (fixed by setup_inputs)
#define DD    768
#define TAGS  5
#define LQ    128
#define BQC   200      // B*N*Q*N
#define BNQ   40       // B*N*Q
#define BNKC  50       // B*N*K
#define NPROT 10       // B*N
#define FD    3072     // 4*D
#define MBIG  25600    // BQC*LQ

// ---------------- scratch (device globals; no allocations allowed) --------------
__device__ float g_protok[BNKC*TAGS*DD];      // per-(b,n,k) prototypes
__device__ float g_proto [NPROT*TAGS*DD];     // averaged prototypes [bn][tag][d]
__device__ float g_pw2   [NPROT*TAGS*DD];     // proto @ W2^T
__device__ float g_att   [BQC*TAGS*LQ];       // att (incl. +100*qmask bias)
__device__ float g_P     [BQC*LQ*TAGS];       // softmax over s, layout [bq][q][s]
__device__ float g_FS    [BQC*TAGS*FD];       // support-side fuse rows
__device__ float g_Ap    [(size_t)MBIG*1536]; // |m1-m2| , m1*m2 features
__device__ float g_T1    [BNQ*LQ*DD];         // query @ W1^T
__device__ float g_es    [BQC*TAGS*DD];
__device__ float g_eqmax [BQC*DD];
__device__ float g_eqsum [BQC*DD];
__device__ float g_cat   [BQC*FD];
__device__ float g_h     [BQC*DD];

__device__ __forceinline__ float warpMax(float v){
    #pragma unroll
    for (int o=16;o;o>>=1) v = fmaxf(v, __shfl_xor_sync(0xffffffffu, v, o));
    return v;
}
__device__ __forceinline__ float warpSum(float v){
    #pragma unroll
    for (int o=16;o;o>>=1) v += __shfl_xor_sync(0xffffffffu, v, o);
    return v;
}

// ---------------- K1: per-(b,n,k) tag prototypes ----------------
__global__ void proto_kernel(const float* __restrict__ s_emb,
                             const float* __restrict__ s_mask,
                             const float* __restrict__ s_label)
{
    int bnk = blockIdx.x, tid = threadIdx.x;
    __shared__ int   tags[128];
    __shared__ float wts[128];
    __shared__ float cnt[TAGS];
    if (tid < 128) {
        const float* lr = s_label + ((size_t)bnk*128 + tid)*TAGS;
        float best = lr[0]; int bi = 0;
        #pragma unroll
        for (int s=1;s<TAGS;s++){ float v = lr[s]; if (v > best){ best = v; bi = s; } }
        tags[tid] = bi;
        wts[tid]  = (bi == 0) ? s_mask[bnk*128 + tid] : 1.0f;
    }
    __syncthreads();
    if (tid < TAGS) {
        float c = 0.f;
        for (int t=0;t<128;t++) if (tags[t] == tid) c += wts[t];
        cnt[tid] = c;
    }
    __syncthreads();
    float acc[TAGS][3];
    #pragma unroll
    for (int k=0;k<TAGS;k++)
        #pragma unroll
        for (int j=0;j<3;j++) acc[k][j] = 0.f;
    const float* eb = s_emb + (size_t)bnk*128*DD;
    for (int t=0;t<128;t++){
        int tg = tags[t]; float w = wts[t];
        #pragma unroll
        for (int j=0;j<3;j++){
            float e = eb[t*DD + tid + j*256];
            #pragma unroll
            for (int k=0;k<TAGS;k++)
                acc[k][j] += ((tg == k) ? w : 0.0f) * e;
        }
    }
    #pragma unroll
    for (int k=0;k<TAGS;k++){
        float c = cnt[k];
        float inv = (c > 0.f) ? (1.0f / fmaxf(c, 1.0f)) : 0.0f;
        #pragma unroll
        for (int j=0;j<3;j++){
            int d = tid + j*256;
            g_protok[((size_t)bnk*TAGS + k)*DD + d] = (c > 0.f) ? acc[k][j]*inv : 0.0f;
        }
    }
}

// ---------------- K2: mean over K shots ----------------
__global__ void proto_avg_kernel()
{
    int i = blockIdx.x*256 + threadIdx.x;   // < 38400
    int pi = i / (TAGS*DD), rem = i % (TAGS*DD);
    float s = 0.f;
    #pragma unroll
    for (int k=0;k<5;k++) s += g_protok[((size_t)(pi*5 + k))*(TAGS*DD) + rem];
    g_proto[i] = s * 0.2f;
}

// ---------------- K3: protoW2 = proto @ W2^T ----------------
__global__ void pw2_kernel(const float* __restrict__ proj_w)
{
    int r = blockIdx.x;     // 0..49 : bn*5 + s
    __shared__ float pr[DD];
    for (int i=threadIdx.x; i<DD; i+=256) pr[i] = g_proto[(size_t)r*DD + i];
    __syncthreads();
    int wid = threadIdx.x >> 5, lane = threadIdx.x & 31;
    for (int d = wid; d < DD; d += 8){
        const float* wr = proj_w + (size_t)d*FD + DD;   // W2 chunk
        float s = 0.f;
        for (int j=lane; j<DD; j+=32) s += pr[j]*wr[j];
        s = warpSum(s);
        if (!lane) g_pw2[(size_t)r*DD + d] = s;
    }
}

// ---------------- attention scores ----------------
__global__ void att_kernel(const float* __restrict__ q_emb,
                           const float* __restrict__ q_mask)
{
    int bq = blockIdx.x;
    int qi = bq / 5;
    int pi = (bq / 100)*5 + (bq % 5);
    __shared__ float ps[TAGS*DD];
    for (int i=threadIdx.x; i<TAGS*DD; i+=256) ps[i] = g_proto[(size_t)pi*TAGS*DD + i];
    __syncthreads();
    int wid = threadIdx.x >> 5, lane = threadIdx.x & 31;
    const float* qb = q_emb + (size_t)qi*128*DD;
    for (int p = wid; p < TAGS*128; p += 8){
        int s = p >> 7, q = p & 127;
        const float* qr = qb + q*DD;
        const float* prr = ps + s*DD;
        float sum = 0.f;
        for (int d=lane; d<DD; d+=32) sum += prr[d]*qr[d];
        sum = warpSum(sum);
        if (!lane) g_att[(size_t)bq*640 + s*128 + q] = sum + q_mask[qi*128 + q]*100.0f;
    }
}

// ---------------- softmax over s (5 values) ----------------
__global__ void softq_kernel()
{
    int t = blockIdx.x*256 + threadIdx.x;   // < 25600
    int bq = t >> 7, q = t & 127;
    float v[TAGS];
    float mx = -3.4e38f;
    #pragma unroll
    for (int s=0;s<TAGS;s++){ v[s] = g_att[(size_t)bq*640 + s*128 + q]; mx = fmaxf(mx, v[s]); }
    float sm = 0.f;
    #pragma unroll
    for (int s=0;s<TAGS;s++){ v[s] = expf(v[s]-mx); sm += v[s]; }
    float inv = 1.0f/sm;
    #pragma unroll
    for (int s=0;s<TAGS;s++) g_P[(size_t)bq*640 + q*5 + s] = v[s]*inv;
}

// ---------------- support_ + fuse rows ----------------
__global__ void supp_kernel(const float* __restrict__ q_emb)
{
    int bq = blockIdx.x, tid = threadIdx.x;
    int qi = bq / 5;
    int pi = (bq / 100)*5 + (bq % 5);
    __shared__ float arow[TAGS][128];
    __shared__ float ps[TAGS][DD];
    __shared__ float sc[8];
    for (int i=tid;i<TAGS*128;i+=256) arow[i>>7][i&127] = g_att[(size_t)bq*640 + i];
    for (int i=tid;i<TAGS*DD;i+=256) (&ps[0][0])[i] = g_proto[(size_t)pi*TAGS*DD + i];
    __syncthreads();
    // softmax over q for each s row
    for (int s=0;s<TAGS;s++){
        float v = (tid<128) ? arow[s][tid] : -3.4e38f;
        float wm = warpMax(v);
        if ((tid&31)==0) sc[tid>>5] = wm;
        __syncthreads();
        float bm = sc[0];
        #pragma unroll
        for (int r=1;r<8;r++) bm = fmaxf(bm, sc[r]);
        float e = (tid<128) ? expf(v-bm) : 0.f;
        float wsm = warpSum(e);
        __syncthreads();
        if ((tid&31)==0) sc[tid>>5] = wsm;
        __syncthreads();
        float bs = sc[0];
        #pragma unroll
        for (int r=1;r<8;r++) bs += sc[r];
        if (tid<128) arow[s][tid] = e / bs;
        __syncthreads();
    }
    float acc[TAGS][3];
    #pragma unroll
    for (int s=0;s<TAGS;s++)
        #pragma unroll
        for (int j=0;j<3;j++) acc[s][j] = 0.f;
    const float* qb = q_emb + (size_t)qi*128*DD;
    for (int q=0;q<128;q++){
        float w0=arow[0][q], w1=arow[1][q], w2=arow[2][q], w3=arow[3][q], w4=arow[4][q];
        #pragma unroll
        for (int j=0;j<3;j++){
            float e = qb[q*DD + tid + j*256];
            acc[0][j]+=w0*e; acc[1][j]+=w1*e; acc[2][j]+=w2*e; acc[3][j]+=w3*e; acc[4][j]+=w4*e;
        }
    }
    #pragma unroll
    for (int j=0;j<3;j++){
        int d = tid + j*256;
        #pragma unroll
        for (int s=0;s<TAGS;s++){
            float m1 = ps[s][d];
            float m2 = acc[s][j];      // smask = 1
            size_t base = ((size_t)(bq*TAGS + s))*FD;
            g_FS[base + d]        = m1;
            g_FS[base + DD + d]   = m2;
            g_FS[base + 2*DD + d] = fabsf(m1 - m2);
            g_FS[base + 3*DD + d] = m1*m2;
        }
    }
}

// ---------------- query-side feature rows: |m1-m2|, m1*m2 ----------------
__global__ void aprime_kernel(const float* __restrict__ q_emb,
                              const float* __restrict__ q_mask)
{
    int row = blockIdx.x;             // 0..25599
    int bq = row >> 7, q = row & 127;
    int qi = bq / 5;
    int pi = (bq / 100)*5 + (bq % 5);
    const float* Pp = g_P + (size_t)bq*640 + q*5;
    float p0=Pp[0], p1=Pp[1], p2=Pp[2], p3=Pp[3], p4=Pp[4];
    float qm = q_mask[qi*128 + q];
    const float* qr = q_emb + ((size_t)qi*128 + q)*DD;
    const float* pr = g_proto + (size_t)pi*TAGS*DD;
    for (int d = threadIdx.x; d < DD; d += 128){
        float m2 = qm * (p0*pr[d] + p1*pr[DD+d] + p2*pr[2*DD+d] + p3*pr[3*DD+d] + p4*pr[4*DD+d]);
        float m1 = qr[d];
        g_Ap[(size_t)row*1536 + d]      = fabsf(m1 - m2);
        g_Ap[(size_t)row*1536 + DD + d] = m1*m2;
    }
}

// ---------------- shared GEMM core ----------------
// MODE 0: T1 = q_emb @ W1^T                 (M=5120, K=768 , store)
// MODE 1: es = relu(FS @ W^T + b)           (M=1000, K=3072, store)
// MODE 2: big: G34 + T1 + t2 + b, relu, reduce max/sum over 128 rows (M=25600, K=1536)
// MODE 3: h = relu(cat @ rel_w1^T + b)      (M=200 , K=3072, store)
template<int MODE>
__global__ void __launch_bounds__(256, 2) gemm_k(const float* __restrict__ Aarg,
                                                 const float* __restrict__ Bw,
                                                 const float* __restrict__ bias,
                                                 const float* __restrict__ q_mask)
{
    constexpr int KDIM = (MODE==0) ? 768 : (MODE==2) ? 1536 : 3072;
    constexpr int BOFF = (MODE==2) ? 1536 : 0;
    constexpr int MDIM = (MODE==0) ? 5120 : (MODE==1) ? 1000 : (MODE==2) ? 25600 : 200;

    const float* A = (MODE==0) ? Aarg : (MODE==1) ? g_FS : (MODE==2) ? g_Ap : g_cat;
    float* C = (MODE==0) ? g_T1 : (MODE==1) ? g_es : g_h;

    __shared__ float As[16][128];
    __shared__ float Bs[16][68];

    int tid = threadIdx.x;
    int tx = tid & 15, ty = tid >> 4;
    int m0 = blockIdx.y * 128, n0 = blockIdx.x * 64;

    float acc[8][4];
    #pragma unroll
    for (int i=0;i<8;i++)
        #pragma unroll
        for (int j=0;j<4;j++) acc[i][j] = 0.f;

    int lm = tid >> 2;            // 0..63
    int lk4 = (tid & 3) * 4;      // 0,4,8,12

    for (int kt = 0; kt < KDIM/16; kt++){
        int kg = kt*16 + lk4;
        float4 a0, a1, b0;
        int gm0 = m0 + lm;
        a0 = (gm0 < MDIM) ? *(const float4*)(A + (size_t)gm0*KDIM + kg) : make_float4(0,0,0,0);
        int gm1 = gm0 + 64;
        a1 = (gm1 < MDIM) ? *(const float4*)(A + (size_t)gm1*KDIM + kg) : make_float4(0,0,0,0);
        b0 = *(const float4*)(Bw + (size_t)(n0 + lm)*FD + BOFF + kg);
        __syncthreads();
        As[lk4+0][lm]=a0.x; As[lk4+1][lm]=a0.y; As[lk4+2][lm]=a0.z; As[lk4+3][lm]=a0.w;
        As[lk4+0][lm+64]=a1.x; As[lk4+1][lm+64]=a1.y; As[lk4+2][lm+64]=a1.z; As[lk4+3][lm+64]=a1.w;
        Bs[lk4+0][lm]=b0.x; Bs[lk4+1][lm]=b0.y; Bs[lk4+2][lm]=b0.z; Bs[lk4+3][lm]=b0.w;
        __syncthreads();
        #pragma unroll
        for (int kk=0;kk<16;kk++){
            float4 av0 = *(const float4*)&As[kk][ty*8];
            float4 av1 = *(const float4*)&As[kk][ty*8+4];
            float4 bv  = *(const float4*)&Bs[kk][tx*4];
            float a[8] = {av0.x,av0.y,av0.z,av0.w,av1.x,av1.y,av1.z,av1.w};
            float b[4] = {bv.x,bv.y,bv.z,bv.w};
            #pragma unroll
            for (int i=0;i<8;i++)
                #pragma unroll
                for (int j=0;j<4;j++) acc[i][j] += a[i]*b[j];
        }
    }

    if (MODE == 0) {
        #pragma unroll
        for (int i=0;i<8;i++){
            int gm = m0 + ty*8 + i;
            #pragma unroll
            for (int j=0;j<4;j++)
                C[(size_t)gm*DD + n0 + tx*4 + j] = acc[i][j];
        }
    } else if (MODE == 1 || MODE == 3) {
        #pragma unroll
        for (int i=0;i<8;i++){
            int gm = m0 + ty*8 + i;
            if (gm < MDIM){
                #pragma unroll
                for (int j=0;j<4;j++){
                    int gn = n0 + tx*4 + j;
                    C[(size_t)gm*DD + gn] = fmaxf(acc[i][j] + bias[gn], 0.f);
                }
            }
        }
    } else {
        // MODE 2: fused epilogue + in-block reduction over 128 q-rows
        int bq = blockIdx.y;
        int qi = bq / 5;
        int pi = (bq / 100)*5 + (bq % 5);
        __syncthreads();
        float* Ps  = &As[0][0];          // 640
        float* Qm  = &As[0][0] + 768;    // 128
        float* PWs = &Bs[0][0];          // 320 : [s*64 + nl]
        for (int i=tid;i<640;i+=256) Ps[i] = g_P[(size_t)bq*640 + i];
        if (tid < 128) Qm[tid] = q_mask[qi*128 + tid];
        for (int i=tid;i<320;i+=256){
            int s = i >> 6, nl = i & 63;
            PWs[i] = g_pw2[((size_t)pi*5 + s)*DD + n0 + nl];
        }
        __syncthreads();
        float lmax[4], lsum[4];
        #pragma unroll
        for (int j=0;j<4;j++){ lmax[j]=0.f; lsum[j]=0.f; }
        #pragma unroll
        for (int i=0;i<8;i++){
            int q = ty*8 + i;
            float qm = Qm[q];
            float p0=Ps[q*5+0], p1=Ps[q*5+1], p2=Ps[q*5+2], p3=Ps[q*5+3], p4=Ps[q*5+4];
            #pragma unroll
            for (int j=0;j<4;j++){
                int nl = tx*4 + j, gn = n0 + nl;
                float t2 = qm*(p0*PWs[nl] + p1*PWs[64+nl] + p2*PWs[128+nl] + p3*PWs[192+nl] + p4*PWs[256+nl]);
                float v = acc[i][j] + g_T1[((size_t)qi*128 + q)*DD + gn] + t2 + bias[gn];
                v = fmaxf(v, 0.f);
                lmax[j] = fmaxf(lmax[j], v);
                lsum[j] += v;
            }
        }
        __syncthreads();
        float* Rmax = &As[0][0];   // 16*64
        float* Rsum = &Bs[0][0];   // 16*64
        #pragma unroll
        for (int j=0;j<4;j++){
            Rmax[ty*64 + tx*4 + j] = lmax[j];
            Rsum[ty*64 + tx*4 + j] = lsum[j];
        }
        __syncthreads();
        if (tid < 64){
            float mx = Rmax[tid], sm = Rsum[tid];
            #pragma unroll
            for (int r=1;r<16;r++){ mx = fmaxf(mx, Rmax[r*64 + tid]); sm += Rsum[r*64 + tid]; }
            g_eqmax[(size_t)bq*DD + n0 + tid] = mx;
            g_eqsum[(size_t)bq*DD + n0 + tid] = sm;
        }
    }
}

// ---------------- cat assembly (es reduce + eq agg) ----------------
__global__ void cat_kernel(const float* __restrict__ q_mask)
{
    int bq = blockIdx.x, tid = threadIdx.x;
    int qi = bq / 5;
    __shared__ float sc[8];
    __shared__ float qs_s;
    float v = (tid < 128) ? q_mask[qi*128 + tid] : 0.f;
    float ws = warpSum(v);
    if ((tid&31)==0) sc[tid>>5] = ws;
    __syncthreads();
    if (tid == 0){
        float q = 0.f;
        #pragma unroll
        for (int r=0;r<8;r++) q += sc[r];
        qs_s = q;
    }
    __syncthreads();
    float qs = qs_s;
    #pragma unroll
    for (int j=0;j<3;j++){
        int d = tid + j*256;
        float mx = 0.f, sm = 0.f;
        #pragma unroll
        for (int s=0;s<TAGS;s++){
            float e = g_es[((size_t)(bq*TAGS + s))*DD + d];
            mx = fmaxf(mx, e); sm += e;
        }
        size_t b = (size_t)bq*FD;
        g_cat[b + d]        = g_eqmax[(size_t)bq*DD + d];
        g_cat[b + DD + d]   = g_eqsum[(size_t)bq*DD + d] / qs;
        g_cat[b + 2*DD + d] = mx;
        g_cat[b + 3*DD + d] = sm * 0.2f;
    }
}

// ---------------- final logits ----------------
__global__ void logits_kernel(const float* __restrict__ rel_w2,
                              const float* __restrict__ rel_b2,
                              float* __restrict__ out)
{
    int g = blockIdx.x*8 + (threadIdx.x >> 5);
    if (g >= BQC) return;
    int lane = threadIdx.x & 31;
    float s = 0.f;
    for (int d=lane; d<DD; d+=32) s += rel_w2[d]*g_h[(size_t)g*DD + d];
    s = warpSum(s);
    if (!lane) out[g] = s + rel_b2[0];
}

// ---------------- launcher ----------------
extern "C" void kernel_launch(void* const* d_in, const int* in_sizes, int n_in,
                              void* d_out, int out_size)
{
    const float* s_emb   = (const float*)d_in[0];
    const float* q_emb   = (const float*)d_in[1];
    const float* s_mask  = (const float*)d_in[2];
    const float* q_mask  = (const float*)d_in[3];
    const float* s_label = (const float*)d_in[4];
    const float* proj_w  = (const float*)d_in[5];
    const float* proj_b  = (const float*)d_in[6];
    const float* rel_w1  = (const float*)d_in[7];
    const float* rel_b1  = (const float*)d_in[8];
    const float* rel_w2  = (const float*)d_in[9];
    const float* rel_b2  = (const float*)d_in[10];
    float* out = (float*)d_out;

    proto_kernel    <<<BNKC, 256>>>(s_emb, s_mask, s_label);
    proto_avg_kernel<<<150, 256>>>();
    pw2_kernel      <<<NPROT*TAGS, 256>>>(proj_w);
    att_kernel      <<<BQC, 256>>>(q_emb, q_mask);
    softq_kernel    <<<100, 256>>>();
    supp_kernel     <<<BQC, 256>>>(q_emb);
    aprime_kernel   <<<MBIG, 128>>>(q_emb, q_mask);
    gemm_k<0>       <<<dim3(12, 40), 256>>>(q_emb, proj_w, nullptr, nullptr);
    gemm_k<2>       <<<dim3(12, 200), 256>>>(nullptr, proj_w, proj_b, q_mask);
    gemm_k<1>       <<<dim3(12, 8), 256>>>(nullptr, proj_w, proj_b, nullptr);
    cat_kernel      <<<BQC, 256>>>(q_mask);
    gemm_k<3>       <<<dim3(12, 2), 256>>>(nullptr, rel_w1, rel_b1, nullptr);
    logits_kernel   <<<25, 256>>>(rel_w2, rel_b2, out);
}

// round 3
// speedup vs baseline: 1.5656x; 1.5656x over previous
#include <cuda_runtime.h>
#include <cuda_bf16.h>
#include <math.h>
#include <stdint.h>

// Problem constants (fixed by setup_inputs)
#define DD    768
#define TAGS  5
#define LQ    128
#define BQC   200      // B*N*Q*N
#define BNQ   40       // B*N*Q
#define BNKC  50       // B*N*K
#define NPROT 10       // B*N
#define FD    3072     // 4*D
#define MBIG  25600    // BQC*LQ

// ---------------- scratch (device globals; no allocations allowed) --------------
__device__ float g_protok[BNKC*TAGS*DD];
__device__ float g_proto [NPROT*TAGS*DD];
__device__ float g_pw2   [NPROT*TAGS*DD];
__device__ float g_att   [BQC*TAGS*LQ];
__device__ float g_P     [BQC*LQ*TAGS];
__device__ float g_FS    [BQC*TAGS*FD];
__device__ __nv_bfloat16 g_Ahi[(size_t)MBIG*1536];
__device__ __nv_bfloat16 g_Alo[(size_t)MBIG*1536];
__device__ __nv_bfloat16 g_Bhi[(size_t)DD*1536];
__device__ __nv_bfloat16 g_Blo[(size_t)DD*1536];
__device__ float g_T1    [BNQ*LQ*DD];
__device__ float g_es    [BQC*TAGS*DD];
__device__ float g_eqmax [BQC*DD];
__device__ float g_eqsum [BQC*DD];
__device__ float g_cat   [BQC*FD];
__device__ float g_h     [BQC*DD];

__device__ __forceinline__ float warpMax(float v){
    #pragma unroll
    for (int o=16;o;o>>=1) v = fmaxf(v, __shfl_xor_sync(0xffffffffu, v, o));
    return v;
}
__device__ __forceinline__ float warpSum(float v){
    #pragma unroll
    for (int o=16;o;o>>=1) v += __shfl_xor_sync(0xffffffffu, v, o);
    return v;
}

// ================= HMMA helpers (baseline PTX; sm_80+, compiles for compute_103) ====
__device__ __forceinline__ uint32_t smem_u32(const void* p) {
    uint32_t a;
    asm("{ .reg .u64 t; cvta.to.shared.u64 t, %1; cvt.u32.u64 %0, t; }" : "=r"(a) : "l"(p));
    return a;
}
__device__ __forceinline__ void cp16(uint32_t dst, const void* src){
    asm volatile("cp.async.cg.shared.global [%0], [%1], 16;" :: "r"(dst), "l"(src) : "memory");
}
__device__ __forceinline__ void cp_commit(){ asm volatile("cp.async.commit_group;" ::: "memory"); }
__device__ __forceinline__ void cp_wait1(){ asm volatile("cp.async.wait_group 1;" ::: "memory"); }
__device__ __forceinline__ void cp_wait0(){ asm volatile("cp.async.wait_group 0;" ::: "memory"); }

__device__ __forceinline__ void ldsm4(uint32_t a, uint32_t* r){
    asm volatile("ldmatrix.sync.aligned.m8n8.x4.shared.b16 {%0,%1,%2,%3}, [%4];"
        : "=r"(r[0]),"=r"(r[1]),"=r"(r[2]),"=r"(r[3]) : "r"(a));
}
__device__ __forceinline__ void mma16816(float* c, const uint32_t* a, const uint32_t* b){
    asm volatile("mma.sync.aligned.m16n8k16.row.col.f32.bf16.bf16.f32 "
        "{%0,%1,%2,%3},{%4,%5,%6,%7},{%8,%9},{%0,%1,%2,%3};"
        : "+f"(c[0]),"+f"(c[1]),"+f"(c[2]),"+f"(c[3])
        : "r"(a[0]),"r"(a[1]),"r"(a[2]),"r"(a[3]), "r"(b[0]),"r"(b[1]));
}

// SMEM tile swizzle: rows of 32 bf16 (64B = 4 x 16B units).
// unit(m, k8) = m*4 + (k8 ^ ((m>>1)&3));  lanes with consecutive m are conflict-free.
__device__ __forceinline__ uint32_t tile_off(int m, int k8){
    return (uint32_t)((m*4 + (k8 ^ ((m>>1)&3))) << 4);
}

// ---------------- K1: per-(b,n,k) tag prototypes ----------------
__global__ void proto_kernel(const float* __restrict__ s_emb,
                             const float* __restrict__ s_mask,
                             const float* __restrict__ s_label)
{
    int bnk = blockIdx.x, tid = threadIdx.x;
    __shared__ int   tags[128];
    __shared__ float wts[128];
    __shared__ float cnt[TAGS];
    if (tid < 128) {
        const float* lr = s_label + ((size_t)bnk*128 + tid)*TAGS;
        float best = lr[0]; int bi = 0;
        #pragma unroll
        for (int s=1;s<TAGS;s++){ float v = lr[s]; if (v > best){ best = v; bi = s; } }
        tags[tid] = bi;
        wts[tid]  = (bi == 0) ? s_mask[bnk*128 + tid] : 1.0f;
    }
    __syncthreads();
    if (tid < TAGS) {
        float c = 0.f;
        for (int t=0;t<128;t++) if (tags[t] == tid) c += wts[t];
        cnt[tid] = c;
    }
    __syncthreads();
    float acc[TAGS][3];
    #pragma unroll
    for (int k=0;k<TAGS;k++)
        #pragma unroll
        for (int j=0;j<3;j++) acc[k][j] = 0.f;
    const float* eb = s_emb + (size_t)bnk*128*DD;
    for (int t=0;t<128;t++){
        int tg = tags[t]; float w = wts[t];
        #pragma unroll
        for (int j=0;j<3;j++){
            float e = eb[t*DD + tid + j*256];
            #pragma unroll
            for (int k=0;k<TAGS;k++)
                acc[k][j] += ((tg == k) ? w : 0.0f) * e;
        }
    }
    #pragma unroll
    for (int k=0;k<TAGS;k++){
        float c = cnt[k];
        float inv = (c > 0.f) ? (1.0f / fmaxf(c, 1.0f)) : 0.0f;
        #pragma unroll
        for (int j=0;j<3;j++){
            int d = tid + j*256;
            g_protok[((size_t)bnk*TAGS + k)*DD + d] = (c > 0.f) ? acc[k][j]*inv : 0.0f;
        }
    }
}

// ---------------- K2: mean over K shots ----------------
__global__ void proto_avg_kernel()
{
    int i = blockIdx.x*256 + threadIdx.x;
    int pi = i / (TAGS*DD), rem = i % (TAGS*DD);
    float s = 0.f;
    #pragma unroll
    for (int k=0;k<5;k++) s += g_protok[((size_t)(pi*5 + k))*(TAGS*DD) + rem];
    g_proto[i] = s * 0.2f;
}

// ---------------- K3: protoW2 = proto @ W2^T ----------------
__global__ void pw2_kernel(const float* __restrict__ proj_w)
{
    int r = blockIdx.x;
    __shared__ float pr[DD];
    for (int i=threadIdx.x; i<DD; i+=256) pr[i] = g_proto[(size_t)r*DD + i];
    __syncthreads();
    int wid = threadIdx.x >> 5, lane = threadIdx.x & 31;
    for (int d = wid; d < DD; d += 8){
        const float* wr = proj_w + (size_t)d*FD + DD;
        float s = 0.f;
        for (int j=lane; j<DD; j+=32) s += pr[j]*wr[j];
        s = warpSum(s);
        if (!lane) g_pw2[(size_t)r*DD + d] = s;
    }
}

// ---------------- attention scores ----------------
__global__ void att_kernel(const float* __restrict__ q_emb,
                           const float* __restrict__ q_mask)
{
    int bq = blockIdx.x;
    int qi = bq / 5;
    int pi = (bq / 100)*5 + (bq % 5);
    __shared__ float ps[TAGS*DD];
    for (int i=threadIdx.x; i<TAGS*DD; i+=256) ps[i] = g_proto[(size_t)pi*TAGS*DD + i];
    __syncthreads();
    int wid = threadIdx.x >> 5, lane = threadIdx.x & 31;
    const float* qb = q_emb + (size_t)qi*128*DD;
    for (int p = wid; p < TAGS*128; p += 8){
        int s = p >> 7, q = p & 127;
        const float* qr = qb + q*DD;
        const float* prr = ps + s*DD;
        float sum = 0.f;
        for (int d=lane; d<DD; d+=32) sum += prr[d]*qr[d];
        sum = warpSum(sum);
        if (!lane) g_att[(size_t)bq*640 + s*128 + q] = sum + q_mask[qi*128 + q]*100.0f;
    }
}

// ---------------- softmax over s (5 values) ----------------
__global__ void softq_kernel()
{
    int t = blockIdx.x*256 + threadIdx.x;
    int bq = t >> 7, q = t & 127;
    float v[TAGS];
    float mx = -3.4e38f;
    #pragma unroll
    for (int s=0;s<TAGS;s++){ v[s] = g_att[(size_t)bq*640 + s*128 + q]; mx = fmaxf(mx, v[s]); }
    float sm = 0.f;
    #pragma unroll
    for (int s=0;s<TAGS;s++){ v[s] = expf(v[s]-mx); sm += v[s]; }
    float inv = 1.0f/sm;
    #pragma unroll
    for (int s=0;s<TAGS;s++) g_P[(size_t)bq*640 + q*5 + s] = v[s]*inv;
}

// ---------------- support_ + fuse rows ----------------
__global__ void supp_kernel(const float* __restrict__ q_emb)
{
    int bq = blockIdx.x, tid = threadIdx.x;
    int qi = bq / 5;
    int pi = (bq / 100)*5 + (bq % 5);
    __shared__ float arow[TAGS][128];
    __shared__ float ps[TAGS][DD];
    __shared__ float sc[8];
    for (int i=tid;i<TAGS*128;i+=256) arow[i>>7][i&127] = g_att[(size_t)bq*640 + i];
    for (int i=tid;i<TAGS*DD;i+=256) (&ps[0][0])[i] = g_proto[(size_t)pi*TAGS*DD + i];
    __syncthreads();
    for (int s=0;s<TAGS;s++){
        float v = (tid<128) ? arow[s][tid] : -3.4e38f;
        float wm = warpMax(v);
        if ((tid&31)==0) sc[tid>>5] = wm;
        __syncthreads();
        float bm = sc[0];
        #pragma unroll
        for (int r=1;r<8;r++) bm = fmaxf(bm, sc[r]);
        float e = (tid<128) ? expf(v-bm) : 0.f;
        float wsm = warpSum(e);
        __syncthreads();
        if ((tid&31)==0) sc[tid>>5] = wsm;
        __syncthreads();
        float bs = sc[0];
        #pragma unroll
        for (int r=1;r<8;r++) bs += sc[r];
        if (tid<128) arow[s][tid] = e / bs;
        __syncthreads();
    }
    float acc[TAGS][3];
    #pragma unroll
    for (int s=0;s<TAGS;s++)
        #pragma unroll
        for (int j=0;j<3;j++) acc[s][j] = 0.f;
    const float* qb = q_emb + (size_t)qi*128*DD;
    for (int q=0;q<128;q++){
        float w0=arow[0][q], w1=arow[1][q], w2=arow[2][q], w3=arow[3][q], w4=arow[4][q];
        #pragma unroll
        for (int j=0;j<3;j++){
            float e = qb[q*DD + tid + j*256];
            acc[0][j]+=w0*e; acc[1][j]+=w1*e; acc[2][j]+=w2*e; acc[3][j]+=w3*e; acc[4][j]+=w4*e;
        }
    }
    #pragma unroll
    for (int j=0;j<3;j++){
        int d = tid + j*256;
        #pragma unroll
        for (int s=0;s<TAGS;s++){
            float m1 = ps[s][d];
            float m2 = acc[s][j];
            size_t base = ((size_t)(bq*TAGS + s))*FD;
            g_FS[base + d]        = m1;
            g_FS[base + DD + d]   = m2;
            g_FS[base + 2*DD + d] = fabsf(m1 - m2);
            g_FS[base + 3*DD + d] = m1*m2;
        }
    }
}

// ---------------- query-side feature rows -> bf16 hi/lo (block per bq) ----------------
__global__ void aprime_kernel(const float* __restrict__ q_emb,
                              const float* __restrict__ q_mask)
{
    int bq = blockIdx.x, tid = threadIdx.x;
    int qi = bq / 5;
    int pi = (bq / 100)*5 + (bq % 5);
    __shared__ float ps[TAGS*DD];
    __shared__ float sP[640];
    __shared__ float sqm[128];
    for (int i=tid;i<TAGS*DD;i+=256) ps[i] = g_proto[(size_t)pi*TAGS*DD + i];
    for (int i=tid;i<640;i+=256) sP[i] = g_P[(size_t)bq*640 + i];
    if (tid < 128) sqm[tid] = q_mask[qi*128 + tid];
    __syncthreads();
    for (int q = 0; q < 128; q++){
        float p0=sP[q*5+0], p1=sP[q*5+1], p2=sP[q*5+2], p3=sP[q*5+3], p4=sP[q*5+4];
        float qm = sqm[q];
        const float* qr = q_emb + ((size_t)qi*128 + q)*DD;
        size_t base = ((size_t)bq*128 + q)*1536;
        for (int d = tid; d < DD; d += 256){
            float m2 = qm * (p0*ps[d] + p1*ps[DD+d] + p2*ps[2*DD+d] + p3*ps[3*DD+d] + p4*ps[4*DD+d]);
            float m1 = qr[d];
            float va = fabsf(m1 - m2);
            float vp = m1*m2;
            __nv_bfloat16 ah = __float2bfloat16(va);
            __nv_bfloat16 al = __float2bfloat16(va - __bfloat162float(ah));
            __nv_bfloat16 ph = __float2bfloat16(vp);
            __nv_bfloat16 pl = __float2bfloat16(vp - __bfloat162float(ph));
            g_Ahi[base + d]      = ah;  g_Alo[base + d]      = al;
            g_Ahi[base + DD + d] = ph;  g_Alo[base + DD + d] = pl;
        }
    }
}

// ---------------- B-matrix bf16 split prep ----------------
__global__ void bprep_kernel(const float* __restrict__ proj_w)
{
    int i = blockIdx.x*256 + threadIdx.x;
    if (i >= DD*1536) return;
    int n = i / 1536, k = i % 1536;
    float v = proj_w[(size_t)n*FD + 1536 + k];
    __nv_bfloat16 h = __float2bfloat16(v);
    __nv_bfloat16 l = __float2bfloat16(v - __bfloat162float(h));
    g_Bhi[(size_t)n*1536 + k] = h;
    g_Blo[(size_t)n*1536 + k] = l;
}

// ---------------- SIMT GEMM (modes 0: T1, 1: es, 3: h) ----------------
template<int MODE>
__global__ void __launch_bounds__(256, 2) gemm_k(const float* __restrict__ Aarg,
                                                 const float* __restrict__ Bw,
                                                 const float* __restrict__ bias)
{
    constexpr int KDIM = (MODE==0) ? 768 : 3072;
    constexpr int MDIM = (MODE==0) ? 5120 : (MODE==1) ? 1000 : 200;

    const float* A = (MODE==0) ? Aarg : (MODE==1) ? g_FS : g_cat;
    float* C = (MODE==0) ? g_T1 : (MODE==1) ? g_es : g_h;

    __shared__ float As[16][128];
    __shared__ float Bs[16][68];

    int tid = threadIdx.x;
    int tx = tid & 15, ty = tid >> 4;
    int m0 = blockIdx.y * 128, n0 = blockIdx.x * 64;

    float acc[8][4];
    #pragma unroll
    for (int i=0;i<8;i++)
        #pragma unroll
        for (int j=0;j<4;j++) acc[i][j] = 0.f;

    int lm = tid >> 2;
    int lk4 = (tid & 3) * 4;

    for (int kt = 0; kt < KDIM/16; kt++){
        int kg = kt*16 + lk4;
        float4 a0, a1, b0;
        int gm0 = m0 + lm;
        a0 = (gm0 < MDIM) ? *(const float4*)(A + (size_t)gm0*KDIM + kg) : make_float4(0,0,0,0);
        int gm1 = gm0 + 64;
        a1 = (gm1 < MDIM) ? *(const float4*)(A + (size_t)gm1*KDIM + kg) : make_float4(0,0,0,0);
        b0 = *(const float4*)(Bw + (size_t)(n0 + lm)*FD + kg);
        __syncthreads();
        As[lk4+0][lm]=a0.x; As[lk4+1][lm]=a0.y; As[lk4+2][lm]=a0.z; As[lk4+3][lm]=a0.w;
        As[lk4+0][lm+64]=a1.x; As[lk4+1][lm+64]=a1.y; As[lk4+2][lm+64]=a1.z; As[lk4+3][lm+64]=a1.w;
        Bs[lk4+0][lm]=b0.x; Bs[lk4+1][lm]=b0.y; Bs[lk4+2][lm]=b0.z; Bs[lk4+3][lm]=b0.w;
        __syncthreads();
        #pragma unroll
        for (int kk=0;kk<16;kk++){
            float4 av0 = *(const float4*)&As[kk][ty*8];
            float4 av1 = *(const float4*)&As[kk][ty*8+4];
            float4 bv  = *(const float4*)&Bs[kk][tx*4];
            float a[8] = {av0.x,av0.y,av0.z,av0.w,av1.x,av1.y,av1.z,av1.w};
            float b[4] = {bv.x,bv.y,bv.z,bv.w};
            #pragma unroll
            for (int i=0;i<8;i++)
                #pragma unroll
                for (int j=0;j<4;j++) acc[i][j] += a[i]*b[j];
        }
    }

    if (MODE == 0) {
        #pragma unroll
        for (int i=0;i<8;i++){
            int gm = m0 + ty*8 + i;
            #pragma unroll
            for (int j=0;j<4;j++)
                C[(size_t)gm*DD + n0 + tx*4 + j] = acc[i][j];
        }
    } else {
        #pragma unroll
        for (int i=0;i<8;i++){
            int gm = m0 + ty*8 + i;
            if (gm < MDIM){
                #pragma unroll
                for (int j=0;j<4;j++){
                    int gn = n0 + tx*4 + j;
                    C[(size_t)gm*DD + gn] = fmaxf(acc[i][j] + bias[gn], 0.f);
                }
            }
        }
    }
}

// ================= Big GEMM via mma.sync bf16 (hi/lo split, 3 products) =========
// per CTA: M=128 (one bq), N=128, K=1536 in chunks of 32, double-buffered cp.async.
// Fused epilogue: +T1 +t2 +bias, relu, then max/sum reduce over the 128 q rows.
#define NCCH  48            // K chunks of 32
#define TBUF  8192          // one 128x32 bf16 tile
#define BUFSZ (4*TBUF)      // Ah, Al, Bh, Bl
#define VSTRIDE 132

__global__ void __launch_bounds__(256) big_mma(const float* __restrict__ q_mask,
                                               const float* __restrict__ proj_b)
{
    extern __shared__ __align__(128) char ds[];
    __shared__ float s_pwr[5*128];
    __shared__ float s_P[640];
    __shared__ float s_qm[128];
    __shared__ float s_bias[128];

    int tid = threadIdx.x;
    int lane = tid & 31, wid = tid >> 5;
    int wm = wid & 1;          // m-half (64)
    int wn = wid >> 1;         // n-tile of 32 (0..3)
    int bq  = blockIdx.y;
    int n0  = blockIdx.x * 128;
    int qi  = bq / 5;
    int pi  = (bq / 100)*5 + (bq % 5);

    uint32_t sbase = smem_u32(ds);

    // epilogue constants
    for (int i = tid; i < 5*128; i += 256){
        int s = i >> 7, c = i & 127;
        s_pwr[i] = g_pw2[((size_t)pi*5 + s)*DD + n0 + c];
    }
    for (int i = tid; i < 640; i += 256) s_P[i] = g_P[(size_t)bq*640 + i];
    if (tid < 128){ s_qm[tid] = q_mask[qi*128 + tid]; s_bias[tid] = proj_b[n0 + tid]; }

    const char* gAh = (const char*)g_Ahi + (size_t)bq*128*3072;
    const char* gAl = (const char*)g_Alo + (size_t)bq*128*3072;
    const char* gBh = (const char*)g_Bhi + (size_t)n0*3072;
    const char* gBl = (const char*)g_Blo + (size_t)n0*3072;

    float acc[4][4][4];
    #pragma unroll
    for (int a=0;a<4;a++)
        #pragma unroll
        for (int b=0;b<4;b++)
            #pragma unroll
            for (int r=0;r<4;r++) acc[a][b][r] = 0.f;

    // per-thread load slots: 2 units each of A/B per (h,l): idx = tid + i*256
    // unit: row = idx>>2 (0..127), k8 = idx&3
    int r0 = tid >> 2, k80 = tid & 3;
    int r1 = (tid+256) >> 2, k81 = tid & 3;   // second unit: rows 64..127
    uint32_t d0 = tile_off(r0, k80);
    uint32_t d1 = tile_off(r1, k81);

    auto issue = [&](int c, int buf){
        size_t koff = (size_t)c*64;
        uint32_t sb = sbase + buf*BUFSZ;
        size_t s0 = (size_t)r0*3072 + koff + k80*16;
        size_t s1 = (size_t)r1*3072 + koff + k81*16;
        cp16(sb + d0,          gAh + s0);  cp16(sb + d1,          gAh + s1);
        cp16(sb + TBUF + d0,   gAl + s0);  cp16(sb + TBUF + d1,   gAl + s1);
        cp16(sb + 2*TBUF + d0, gBh + s0);  cp16(sb + 2*TBUF + d1, gBh + s1);
        cp16(sb + 3*TBUF + d0, gBl + s0);  cp16(sb + 3*TBUF + d1, gBl + s1);
        cp_commit();
    };

    issue(0, 0);

    // ldmatrix lane addressing
    int a_m  = (lane & 15);          // + m0
    int a_k8 = (lane >> 4);          // + ks8
    int b_n  = (lane & 7) + ((lane >> 4) << 3);   // + n-tile base
    int b_k8 = (lane >> 3) & 1;      // + ks8

    for (int c = 0; c < NCCH; c++){
        int buf = c & 1;
        if (c + 1 < NCCH){ issue(c+1, buf^1); cp_wait1(); }
        else cp_wait0();
        __syncthreads();
        uint32_t ah = sbase + buf*BUFSZ;
        uint32_t al = ah + TBUF;
        uint32_t bh = ah + 2*TBUF;
        uint32_t bl = ah + 3*TBUF;
        #pragma unroll
        for (int ks = 0; ks < 2; ks++){
            int ks8 = ks*2;
            uint32_t Ah[4][4], Al[4][4], Bh[2][4], Bl[2][4];
            #pragma unroll
            for (int mt=0; mt<4; mt++){
                int m = wm*64 + mt*16 + a_m;
                uint32_t off = tile_off(m, ks8 + a_k8);
                ldsm4(ah + off, Ah[mt]);
                ldsm4(al + off, Al[mt]);
            }
            #pragma unroll
            for (int p=0; p<2; p++){
                int n = wn*32 + p*16 + b_n;
                uint32_t off = tile_off(n, ks8 + b_k8);
                ldsm4(bh + off, Bh[p]);
                ldsm4(bl + off, Bl[p]);
            }
            #pragma unroll
            for (int mt=0; mt<4; mt++)
                #pragma unroll
                for (int nt=0; nt<4; nt++)
                    mma16816(acc[mt][nt], Ah[mt], &Bh[nt>>1][(nt&1)*2]);
            #pragma unroll
            for (int mt=0; mt<4; mt++)
                #pragma unroll
                for (int nt=0; nt<4; nt++)
                    mma16816(acc[mt][nt], Ah[mt], &Bl[nt>>1][(nt&1)*2]);
            #pragma unroll
            for (int mt=0; mt<4; mt++)
                #pragma unroll
                for (int nt=0; nt<4; nt++)
                    mma16816(acc[mt][nt], Al[mt], &Bh[nt>>1][(nt&1)*2]);
        }
        __syncthreads();
    }

    // ---- fused epilogue ----
    float* vbuf = (float*)ds;   // [128 q][VSTRIDE]
    int row = lane >> 2, colb = (lane & 3)*2;
    #pragma unroll
    for (int mt=0; mt<4; mt++){
        #pragma unroll
        for (int h2=0; h2<2; h2++){
            int q = wm*64 + mt*16 + row + h2*8;
            float qm = s_qm[q];
            float p0=s_P[q*5+0], p1=s_P[q*5+1], p2=s_P[q*5+2], p3=s_P[q*5+3], p4=s_P[q*5+4];
            const float* t1row = g_T1 + ((size_t)qi*128 + q)*DD + n0;
            #pragma unroll
            for (int nt=0; nt<4; nt++){
                int cl = wn*32 + nt*8 + colb;
                float2 t1 = *(const float2*)(t1row + cl);
                float t2a = qm*(p0*s_pwr[cl] + p1*s_pwr[128+cl] + p2*s_pwr[256+cl]
                              + p3*s_pwr[384+cl] + p4*s_pwr[512+cl]);
                float t2b = qm*(p0*s_pwr[cl+1] + p1*s_pwr[128+cl+1] + p2*s_pwr[256+cl+1]
                              + p3*s_pwr[384+cl+1] + p4*s_pwr[512+cl+1]);
                float v0 = fmaxf(acc[mt][nt][h2*2+0] + t1.x + t2a + s_bias[cl], 0.f);
                float v1 = fmaxf(acc[mt][nt][h2*2+1] + t1.y + t2b + s_bias[cl+1], 0.f);
                vbuf[q*VSTRIDE + cl]     = v0;
                vbuf[q*VSTRIDE + cl + 1] = v1;
            }
        }
    }
    __syncthreads();
    if (tid < 128){
        float mx = 0.f, sm = 0.f;
        #pragma unroll 8
        for (int qq = 0; qq < 128; qq++){
            float v = vbuf[qq*VSTRIDE + tid];
            mx = fmaxf(mx, v); sm += v;
        }
        g_eqmax[(size_t)bq*DD + n0 + tid] = mx;
        g_eqsum[(size_t)bq*DD + n0 + tid] = sm;
    }
}

// ---------------- cat assembly (es reduce + eq agg) ----------------
__global__ void cat_kernel(const float* __restrict__ q_mask)
{
    int bq = blockIdx.x, tid = threadIdx.x;
    int qi = bq / 5;
    __shared__ float sc[8];
    __shared__ float qs_s;
    float v = (tid < 128) ? q_mask[qi*128 + tid] : 0.f;
    float ws = warpSum(v);
    if ((tid&31)==0) sc[tid>>5] = ws;
    __syncthreads();
    if (tid == 0){
        float q = 0.f;
        #pragma unroll
        for (int r=0;r<8;r++) q += sc[r];
        qs_s = q;
    }
    __syncthreads();
    float qs = qs_s;
    #pragma unroll
    for (int j=0;j<3;j++){
        int d = tid + j*256;
        float mx = 0.f, sm = 0.f;
        #pragma unroll
        for (int s=0;s<TAGS;s++){
            float e = g_es[((size_t)(bq*TAGS + s))*DD + d];
            mx = fmaxf(mx, e); sm += e;
        }
        size_t b = (size_t)bq*FD;
        g_cat[b + d]        = g_eqmax[(size_t)bq*DD + d];
        g_cat[b + DD + d]   = g_eqsum[(size_t)bq*DD + d] / qs;
        g_cat[b + 2*DD + d] = mx;
        g_cat[b + 3*DD + d] = sm * 0.2f;
    }
}

// ---------------- final logits ----------------
__global__ void logits_kernel(const float* __restrict__ rel_w2,
                              const float* __restrict__ rel_b2,
                              float* __restrict__ out)
{
    int g = blockIdx.x*8 + (threadIdx.x >> 5);
    if (g >= BQC) return;
    int lane = threadIdx.x & 31;
    float s = 0.f;
    for (int d=lane; d<DD; d+=32) s += rel_w2[d]*g_h[(size_t)g*DD + d];
    s = warpSum(s);
    if (!lane) out[g] = s + rel_b2[0];
}

// ---------------- launcher ----------------
extern "C" void kernel_launch(void* const* d_in, const int* in_sizes, int n_in,
                              void* d_out, int out_size)
{
    const float* s_emb   = (const float*)d_in[0];
    const float* q_emb   = (const float*)d_in[1];
    const float* s_mask  = (const float*)d_in[2];
    const float* q_mask  = (const float*)d_in[3];
    const float* s_label = (const float*)d_in[4];
    const float* proj_w  = (const float*)d_in[5];
    const float* proj_b  = (const float*)d_in[6];
    const float* rel_w1  = (const float*)d_in[7];
    const float* rel_b1  = (const float*)d_in[8];
    const float* rel_w2  = (const float*)d_in[9];
    const float* rel_b2  = (const float*)d_in[10];
    float* out = (float*)d_out;

    static bool attr_set = false;
    if (!attr_set){
        cudaFuncSetAttribute(big_mma, cudaFuncAttributeMaxDynamicSharedMemorySize, 128*VSTRIDE*4);
        attr_set = true;
    }

    proto_kernel    <<<BNKC, 256>>>(s_emb, s_mask, s_label);
    proto_avg_kernel<<<150, 256>>>();
    bprep_kernel    <<<(DD*1536 + 255)/256, 256>>>(proj_w);
    pw2_kernel      <<<NPROT*TAGS, 256>>>(proj_w);
    att_kernel      <<<BQC, 256>>>(q_emb, q_mask);
    softq_kernel    <<<100, 256>>>();
    supp_kernel     <<<BQC, 256>>>(q_emb);
    aprime_kernel   <<<BQC, 256>>>(q_emb, q_mask);
    gemm_k<0>       <<<dim3(12, 40), 256>>>(q_emb, proj_w, nullptr);
    big_mma         <<<dim3(6, 200), 256, 128*VSTRIDE*4>>>(q_mask, proj_b);
    gemm_k<1>       <<<dim3(12, 8), 256>>>(nullptr, proj_w, proj_b);
    cat_kernel      <<<BQC, 256>>>(q_mask);
    gemm_k<3>       <<<dim3(12, 2), 256>>>(nullptr, rel_w1, rel_b1);
    logits_kernel   <<<25, 256>>>(rel_w2, rel_b2, out);
}

// round 5
// speedup vs baseline: 2.2052x; 1.4085x over previous
#include <cuda_runtime.h>
#include <cuda_bf16.h>
#include <math.h>
#include <stdint.h>

// Problem constants (fixed by setup_inputs)
#define DD    768
#define TAGS  5
#define LQ    128
#define BQC   200      // B*N*Q*N
#define BNQ   40       // B*N*Q
#define BNKC  50       // B*N*K
#define NPROT 10       // B*N
#define FD    3072     // 4*D
#define MBIG  25600    // BQC*LQ

// ---------------- scratch (device globals) --------------
__device__ float g_protok[BNKC*TAGS*DD];
__device__ float g_proto [NPROT*TAGS*DD];
__device__ float g_pw2   [NPROT*TAGS*DD];
__device__ float g_att   [BQC*TAGS*LQ];
__device__ float g_P     [BQC*LQ*TAGS];
__device__ __nv_bfloat16 g_Ahi[(size_t)MBIG*1536];
__device__ __nv_bfloat16 g_Alo[(size_t)MBIG*1536];
__device__ __nv_bfloat16 g_Wh [(size_t)DD*FD];      // proj_w split
__device__ __nv_bfloat16 g_Wl [(size_t)DD*FD];
__device__ __nv_bfloat16 g_RWh[(size_t)DD*FD];      // rel_w1 split
__device__ __nv_bfloat16 g_RWl[(size_t)DD*FD];
__device__ __nv_bfloat16 g_Qh [(size_t)BNQ*LQ*DD];  // q_emb split
__device__ __nv_bfloat16 g_Ql [(size_t)BNQ*LQ*DD];
__device__ __nv_bfloat16 g_FSh[(size_t)1024*FD];    // fuse-support rows (padded 1000->1024)
__device__ __nv_bfloat16 g_FSl[(size_t)1024*FD];
__device__ __nv_bfloat16 g_Ch [(size_t)256*FD];     // cat rows (padded 200->256)
__device__ __nv_bfloat16 g_Cl [(size_t)256*FD];
__device__ float g_T1    [BNQ*LQ*DD];
__device__ float g_es    [BQC*TAGS*DD];
__device__ float g_eqmax [BQC*DD];
__device__ float g_eqsum [BQC*DD];
__device__ float g_h     [BQC*DD];

__device__ __forceinline__ float warpMax(float v){
    #pragma unroll
    for (int o=16;o;o>>=1) v = fmaxf(v, __shfl_xor_sync(0xffffffffu, v, o));
    return v;
}
__device__ __forceinline__ float warpSum(float v){
    #pragma unroll
    for (int o=16;o;o>>=1) v += __shfl_xor_sync(0xffffffffu, v, o);
    return v;
}

// ================= HMMA helpers (baseline PTX) ====
__device__ __forceinline__ uint32_t smem_u32(const void* p) {
    uint32_t a;
    asm("{ .reg .u64 t; cvta.to.shared.u64 t, %1; cvt.u32.u64 %0, t; }" : "=r"(a) : "l"(p));
    return a;
}
__device__ __forceinline__ void cp16(uint32_t dst, const void* src){
    asm volatile("cp.async.cg.shared.global [%0], [%1], 16;" :: "r"(dst), "l"(src) : "memory");
}
__device__ __forceinline__ void cp_commit(){ asm volatile("cp.async.commit_group;" ::: "memory"); }
template<int N> __device__ __forceinline__ void cp_waitg(){
    asm volatile("cp.async.wait_group %0;" :: "n"(N) : "memory");
}
__device__ __forceinline__ void ldsm4(uint32_t a, uint32_t* r){
    asm volatile("ldmatrix.sync.aligned.m8n8.x4.shared.b16 {%0,%1,%2,%3}, [%4];"
        : "=r"(r[0]),"=r"(r[1]),"=r"(r[2]),"=r"(r[3]) : "r"(a));
}
__device__ __forceinline__ void mma16816(float* c, const uint32_t* a, const uint32_t* b){
    asm volatile("mma.sync.aligned.m16n8k16.row.col.f32.bf16.bf16.f32 "
        "{%0,%1,%2,%3},{%4,%5,%6,%7},{%8,%9},{%0,%1,%2,%3};"
        : "+f"(c[0]),"+f"(c[1]),"+f"(c[2]),"+f"(c[3])
        : "r"(a[0]),"r"(a[1]),"r"(a[2]),"r"(a[3]), "r"(b[0]),"r"(b[1]));
}
// SMEM tile swizzle for 128x32 bf16 tiles (rows of 64B = 4 x 16B units)
__device__ __forceinline__ uint32_t tile_off(int m, int k8){
    return (uint32_t)((m*4 + (k8 ^ ((m>>1)&3))) << 4);
}

// ---------------- K1: per-(b,n,k) tag prototypes ----------------
__global__ void proto_kernel(const float* __restrict__ s_emb,
                             const float* __restrict__ s_mask,
                             const float* __restrict__ s_label)
{
    int bnk = blockIdx.x, tid = threadIdx.x;
    __shared__ int   tags[128];
    __shared__ float wts[128];
    __shared__ float cnt[TAGS];
    if (tid < 128) {
        const float* lr = s_label + ((size_t)bnk*128 + tid)*TAGS;
        float best = lr[0]; int bi = 0;
        #pragma unroll
        for (int s=1;s<TAGS;s++){ float v = lr[s]; if (v > best){ best = v; bi = s; } }
        tags[tid] = bi;
        wts[tid]  = (bi == 0) ? s_mask[bnk*128 + tid] : 1.0f;
    }
    __syncthreads();
    if (tid < TAGS) {
        float c = 0.f;
        for (int t=0;t<128;t++) if (tags[t] == tid) c += wts[t];
        cnt[tid] = c;
    }
    __syncthreads();
    float acc[TAGS][3];
    #pragma unroll
    for (int k=0;k<TAGS;k++)
        #pragma unroll
        for (int j=0;j<3;j++) acc[k][j] = 0.f;
    const float* eb = s_emb + (size_t)bnk*128*DD;
    for (int t=0;t<128;t++){
        int tg = tags[t]; float w = wts[t];
        #pragma unroll
        for (int j=0;j<3;j++){
            float e = eb[t*DD + tid + j*256];
            #pragma unroll
            for (int k=0;k<TAGS;k++)
                acc[k][j] += ((tg == k) ? w : 0.0f) * e;
        }
    }
    #pragma unroll
    for (int k=0;k<TAGS;k++){
        float c = cnt[k];
        float inv = (c > 0.f) ? (1.0f / fmaxf(c, 1.0f)) : 0.0f;
        #pragma unroll
        for (int j=0;j<3;j++){
            int d = tid + j*256;
            g_protok[((size_t)bnk*TAGS + k)*DD + d] = (c > 0.f) ? acc[k][j]*inv : 0.0f;
        }
    }
}

// ---------------- K2: mean over K shots ----------------
__global__ void proto_avg_kernel()
{
    int i = blockIdx.x*256 + threadIdx.x;
    int pi = i / (TAGS*DD), rem = i % (TAGS*DD);
    float s = 0.f;
    #pragma unroll
    for (int k=0;k<5;k++) s += g_protok[((size_t)(pi*5 + k))*(TAGS*DD) + rem];
    g_proto[i] = s * 0.2f;
}

// ---------------- generic bf16 hi/lo split ----------------
__global__ void split_kernel(const float* __restrict__ src,
                             __nv_bfloat16* __restrict__ h,
                             __nv_bfloat16* __restrict__ l, int n)
{
    int i = blockIdx.x*256 + threadIdx.x;
    if (i >= n) return;
    float v = src[i];
    __nv_bfloat16 hh = __float2bfloat16(v);
    h[i] = hh;
    l[i] = __float2bfloat16(v - __bfloat162float(hh));
}

// ---------------- pw2 = proto @ W2^T (M=50, N=768, K=768), tiled SIMT ----------------
__global__ void __launch_bounds__(256) pw2_gemm(const float* __restrict__ Bw)  // Bw = proj_w + 768
{
    __shared__ float As[16][52];
    __shared__ float Bs[16][68];
    int tid = threadIdx.x;
    int tx = tid & 15, ty = tid >> 4;
    int n0 = blockIdx.x * 64;
    float acc[4][4];
    #pragma unroll
    for (int i=0;i<4;i++)
        #pragma unroll
        for (int j=0;j<4;j++) acc[i][j] = 0.f;
    int lm = tid >> 2, lk4 = (tid & 3)*4;
    for (int kt = 0; kt < 48; kt++){
        int kg = kt*16 + lk4;
        float4 a0 = (lm < 50) ? *(const float4*)(g_proto + (size_t)lm*DD + kg) : make_float4(0,0,0,0);
        float4 b0 = *(const float4*)(Bw + (size_t)(n0 + lm)*FD + kg);
        __syncthreads();
        if (lm < 50){
            As[lk4+0][lm]=a0.x; As[lk4+1][lm]=a0.y; As[lk4+2][lm]=a0.z; As[lk4+3][lm]=a0.w;
        }
        Bs[lk4+0][lm]=b0.x; Bs[lk4+1][lm]=b0.y; Bs[lk4+2][lm]=b0.z; Bs[lk4+3][lm]=b0.w;
        __syncthreads();
        if (ty < 13){
            #pragma unroll
            for (int kk=0;kk<16;kk++){
                float a[4], b[4];
                #pragma unroll
                for (int i=0;i<4;i++) a[i] = (ty*4+i < 50) ? As[kk][ty*4+i] : 0.f;
                float4 bv = *(const float4*)&Bs[kk][tx*4];
                b[0]=bv.x; b[1]=bv.y; b[2]=bv.z; b[3]=bv.w;
                #pragma unroll
                for (int i=0;i<4;i++)
                    #pragma unroll
                    for (int j=0;j<4;j++) acc[i][j] += a[i]*b[j];
            }
        }
    }
    #pragma unroll
    for (int i=0;i<4;i++){
        int gm = ty*4 + i;
        if (gm < 50){
            #pragma unroll
            for (int j=0;j<4;j++)
                g_pw2[(size_t)gm*DD + n0 + tx*4 + j] = acc[i][j];
        }
    }
}

// ---------------- attention scores: block per qi ----------------
__global__ void __launch_bounds__(256) att_kernel(const float* __restrict__ q_emb,
                                                  const float* __restrict__ q_mask)
{
    extern __shared__ float sp[];        // 25 proto rows x 768
    int qi = blockIdx.x, tid = threadIdx.x;
    int b = qi / 20;
    const float* pb = g_proto + (size_t)b*25*DD;
    for (int i = tid; i < 25*DD; i += 256) sp[i] = pb[i];
    __syncthreads();
    int wid = tid >> 5, lane = tid & 31;
    const float4* sp4 = (const float4*)sp;
    for (int r = wid; r < 128; r += 8){
        const float4* qr4 = (const float4*)(q_emb + ((size_t)qi*128 + r)*DD);
        float acc[25];
        #pragma unroll
        for (int t=0;t<25;t++) acc[t] = 0.f;
        for (int d4 = lane; d4 < 192; d4 += 32){
            float4 qv = qr4[d4];
            #pragma unroll
            for (int t=0;t<25;t++){
                float4 sv = sp4[t*192 + d4];
                acc[t] += qv.x*sv.x + qv.y*sv.y + qv.z*sv.z + qv.w*sv.w;
            }
        }
        float qmb = q_mask[qi*128 + r]*100.0f;
        #pragma unroll
        for (int t=0;t<25;t++){
            float s = warpSum(acc[t]);
            if (lane == (t & 31)){
                int c = t / 5, sg = t % 5;
                g_att[(size_t)(qi*5 + c)*640 + sg*128 + r] = s + qmb;
            }
        }
    }
}

// ---------------- softmax over s (5 values) ----------------
__global__ void softq_kernel()
{
    int t = blockIdx.x*256 + threadIdx.x;
    int bq = t >> 7, q = t & 127;
    float v[TAGS];
    float mx = -3.4e38f;
    #pragma unroll
    for (int s=0;s<TAGS;s++){ v[s] = g_att[(size_t)bq*640 + s*128 + q]; mx = fmaxf(mx, v[s]); }
    float sm = 0.f;
    #pragma unroll
    for (int s=0;s<TAGS;s++){ v[s] = expf(v[s]-mx); sm += v[s]; }
    float inv = 1.0f/sm;
    #pragma unroll
    for (int s=0;s<TAGS;s++) g_P[(size_t)bq*640 + q*5 + s] = v[s]*inv;
}

// ---------------- support_ + fuse rows (writes bf16 hi/lo) ----------------
__global__ void supp_kernel(const float* __restrict__ q_emb)
{
    int bq = blockIdx.x, tid = threadIdx.x;
    int qi = bq / 5;
    int pi = (bq / 100)*5 + (bq % 5);
    __shared__ float arow[TAGS][128];
    __shared__ float ps[TAGS][DD];
    __shared__ float sc[8];
    for (int i=tid;i<TAGS*128;i+=256) arow[i>>7][i&127] = g_att[(size_t)bq*640 + i];
    for (int i=tid;i<TAGS*DD;i+=256) (&ps[0][0])[i] = g_proto[(size_t)pi*TAGS*DD + i];
    __syncthreads();
    for (int s=0;s<TAGS;s++){
        float v = (tid<128) ? arow[s][tid] : -3.4e38f;
        float wm = warpMax(v);
        if ((tid&31)==0) sc[tid>>5] = wm;
        __syncthreads();
        float bm = sc[0];
        #pragma unroll
        for (int r=1;r<8;r++) bm = fmaxf(bm, sc[r]);
        float e = (tid<128) ? expf(v-bm) : 0.f;
        float wsm = warpSum(e);
        __syncthreads();
        if ((tid&31)==0) sc[tid>>5] = wsm;
        __syncthreads();
        float bs = sc[0];
        #pragma unroll
        for (int r=1;r<8;r++) bs += sc[r];
        if (tid<128) arow[s][tid] = e / bs;
        __syncthreads();
    }
    float acc[TAGS][3];
    #pragma unroll
    for (int s=0;s<TAGS;s++)
        #pragma unroll
        for (int j=0;j<3;j++) acc[s][j] = 0.f;
    const float* qb = q_emb + (size_t)qi*128*DD;
    for (int q=0;q<128;q++){
        float w0=arow[0][q], w1=arow[1][q], w2=arow[2][q], w3=arow[3][q], w4=arow[4][q];
        #pragma unroll
        for (int j=0;j<3;j++){
            float e = qb[q*DD + tid + j*256];
            acc[0][j]+=w0*e; acc[1][j]+=w1*e; acc[2][j]+=w2*e; acc[3][j]+=w3*e; acc[4][j]+=w4*e;
        }
    }
    #pragma unroll
    for (int j=0;j<3;j++){
        int d = tid + j*256;
        #pragma unroll
        for (int s=0;s<TAGS;s++){
            float m1 = ps[s][d];
            float m2 = acc[s][j];
            float f[4] = { m1, m2, fabsf(m1-m2), m1*m2 };
            size_t base = ((size_t)(bq*TAGS + s))*FD;
            #pragma unroll
            for (int cchunk=0;cchunk<4;cchunk++){
                float v = f[cchunk];
                __nv_bfloat16 hh = __float2bfloat16(v);
                g_FSh[base + cchunk*DD + d] = hh;
                g_FSl[base + cchunk*DD + d] = __float2bfloat16(v - __bfloat162float(hh));
            }
        }
    }
}

// ---------------- query-side feature rows -> bf16 hi/lo (block per bq) ----------------
__global__ void aprime_kernel(const float* __restrict__ q_emb,
                              const float* __restrict__ q_mask)
{
    int bq = blockIdx.x, tid = threadIdx.x;
    int qi = bq / 5;
    int pi = (bq / 100)*5 + (bq % 5);
    __shared__ float ps[TAGS*DD];
    __shared__ float sP[640];
    __shared__ float sqm[128];
    for (int i=tid;i<TAGS*DD;i+=256) ps[i] = g_proto[(size_t)pi*TAGS*DD + i];
    for (int i=tid;i<640;i+=256) sP[i] = g_P[(size_t)bq*640 + i];
    if (tid < 128) sqm[tid] = q_mask[qi*128 + tid];
    __syncthreads();
    for (int q = 0; q < 128; q++){
        float p0=sP[q*5+0], p1=sP[q*5+1], p2=sP[q*5+2], p3=sP[q*5+3], p4=sP[q*5+4];
        float qm = sqm[q];
        const float* qr = q_emb + ((size_t)qi*128 + q)*DD;
        size_t base = ((size_t)bq*128 + q)*1536;
        for (int d = tid; d < DD; d += 256){
            float m2 = qm * (p0*ps[d] + p1*ps[DD+d] + p2*ps[2*DD+d] + p3*ps[3*DD+d] + p4*ps[4*DD+d]);
            float m1 = qr[d];
            float va = fabsf(m1 - m2);
            float vp = m1*m2;
            __nv_bfloat16 ah = __float2bfloat16(va);
            __nv_bfloat16 al = __float2bfloat16(va - __bfloat162float(ah));
            __nv_bfloat16 ph = __float2bfloat16(vp);
            __nv_bfloat16 pl = __float2bfloat16(vp - __bfloat162float(ph));
            g_Ahi[base + d]      = ah;  g_Alo[base + d]      = al;
            g_Ahi[base + DD + d] = ph;  g_Alo[base + DD + d] = pl;
        }
    }
}

// ================= generic HMMA GEMM: C = [relu](A @ B^T [+ bias]) =========
#define TBUF  8192
#define STGSZ (4*TBUF)

template<int KDIM, int MDIM, bool RELU>
__global__ void __launch_bounds__(256) hgemm(const __nv_bfloat16* __restrict__ Ah_,
                                             const __nv_bfloat16* __restrict__ Al_,
                                             const __nv_bfloat16* __restrict__ Bh_,
                                             const __nv_bfloat16* __restrict__ Bl_,
                                             float* __restrict__ C,
                                             const float* __restrict__ bias)
{
    constexpr int NC = KDIM / 32;
    extern __shared__ __align__(128) char ds[];
    int tid = threadIdx.x;
    int lane = tid & 31, wid = tid >> 5;
    int wm = wid & 1, wn = wid >> 1;
    int m0 = blockIdx.y * 128, n0 = blockIdx.x * 128;
    uint32_t sbase = smem_u32(ds);

    const char* gAh = (const char*)Ah_ + (size_t)m0*KDIM*2;
    const char* gAl = (const char*)Al_ + (size_t)m0*KDIM*2;
    const char* gBh = (const char*)Bh_ + (size_t)n0*FD*2;
    const char* gBl = (const char*)Bl_ + (size_t)n0*FD*2;

    float acc[4][4][4];
    #pragma unroll
    for (int a=0;a<4;a++)
        #pragma unroll
        for (int b=0;b<4;b++)
            #pragma unroll
            for (int r=0;r<4;r++) acc[a][b][r] = 0.f;

    int r0 = tid >> 2, k80 = tid & 3;
    int r1 = r0 + 64;
    uint32_t d0 = tile_off(r0, k80);
    uint32_t d1 = tile_off(r1, k80);

    auto issue = [&](int c, int buf){
        size_t koff = (size_t)c*64 + (size_t)k80*16;   // FIX: per-thread k-unit offset
        uint32_t sb = sbase + buf*STGSZ;
        size_t sa0 = (size_t)r0*(KDIM*2) + koff;
        size_t sa1 = (size_t)r1*(KDIM*2) + koff;
        size_t sb0 = (size_t)r0*(FD*2) + koff;
        size_t sb1 = (size_t)r1*(FD*2) + koff;
        cp16(sb + d0,          gAh + sa0);  cp16(sb + d1,          gAh + sa1);
        cp16(sb + TBUF + d0,   gAl + sa0);  cp16(sb + TBUF + d1,   gAl + sa1);
        cp16(sb + 2*TBUF + d0, gBh + sb0);  cp16(sb + 2*TBUF + d1, gBh + sb1);
        cp16(sb + 3*TBUF + d0, gBl + sb0);  cp16(sb + 3*TBUF + d1, gBl + sb1);
        cp_commit();
    };

    issue(0, 0);
    issue(1, 1);

    int a_m  = (lane & 15);
    int a_k8 = (lane >> 4);
    int b_n  = (lane & 7) + ((lane >> 4) << 3);
    int b_k8 = (lane >> 3) & 1;

    for (int c = 0; c < NC; c++){
        if (c + 2 < NC){ issue(c+2, (c+2)%3); cp_waitg<2>(); }
        else if (c + 1 < NC) cp_waitg<1>();
        else cp_waitg<0>();
        __syncthreads();
        uint32_t ah = sbase + (c%3)*STGSZ;
        uint32_t al = ah + TBUF;
        uint32_t bh = ah + 2*TBUF;
        uint32_t bl = ah + 3*TBUF;
        #pragma unroll
        for (int ks = 0; ks < 2; ks++){
            int ks8 = ks*2;
            uint32_t Ahf[4][4], Alf[4][4], Bhf[2][4], Blf[2][4];
            #pragma unroll
            for (int mt=0; mt<4; mt++){
                int m = wm*64 + mt*16 + a_m;
                uint32_t off = tile_off(m, ks8 + a_k8);
                ldsm4(ah + off, Ahf[mt]);
                ldsm4(al + off, Alf[mt]);
            }
            #pragma unroll
            for (int p=0; p<2; p++){
                int n = wn*32 + p*16 + b_n;
                uint32_t off = tile_off(n, ks8 + b_k8);
                ldsm4(bh + off, Bhf[p]);
                ldsm4(bl + off, Blf[p]);
            }
            #pragma unroll
            for (int mt=0; mt<4; mt++)
                #pragma unroll
                for (int nt=0; nt<4; nt++)
                    mma16816(acc[mt][nt], Ahf[mt], &Bhf[nt>>1][(nt&1)*2]);
            #pragma unroll
            for (int mt=0; mt<4; mt++)
                #pragma unroll
                for (int nt=0; nt<4; nt++)
                    mma16816(acc[mt][nt], Ahf[mt], &Blf[nt>>1][(nt&1)*2]);
            #pragma unroll
            for (int mt=0; mt<4; mt++)
                #pragma unroll
                for (int nt=0; nt<4; nt++)
                    mma16816(acc[mt][nt], Alf[mt], &Bhf[nt>>1][(nt&1)*2]);
        }
        __syncthreads();
    }

    int row = lane >> 2, colb = (lane & 3)*2;
    #pragma unroll
    for (int mt=0; mt<4; mt++){
        #pragma unroll
        for (int h2=0; h2<2; h2++){
            int gm = m0 + wm*64 + mt*16 + row + h2*8;
            if (gm < MDIM){
                #pragma unroll
                for (int nt=0; nt<4; nt++){
                    int cl = wn*32 + nt*8 + colb;
                    int gn = n0 + cl;
                    float v0 = acc[mt][nt][h2*2+0];
                    float v1 = acc[mt][nt][h2*2+1];
                    if (RELU){
                        v0 = fmaxf(v0 + bias[gn], 0.f);
                        v1 = fmaxf(v1 + bias[gn+1], 0.f);
                    }
                    C[(size_t)gm*DD + gn]   = v0;
                    C[(size_t)gm*DD + gn+1] = v1;
                }
            }
        }
    }
}

// ================= Big GEMM via mma.sync bf16 (hi/lo split, fused epilogue) =========
#define NCCH  48
#define VSTRIDE 132

__global__ void __launch_bounds__(256) big_mma(const float* __restrict__ q_mask,
                                               const float* __restrict__ proj_b)
{
    extern __shared__ __align__(128) char ds[];
    __shared__ float s_pwr[5*128];
    __shared__ float s_P[640];
    __shared__ float s_qm[128];
    __shared__ float s_bias[128];

    int tid = threadIdx.x;
    int lane = tid & 31, wid = tid >> 5;
    int wm = wid & 1;
    int wn = wid >> 1;
    int bq  = blockIdx.y;
    int n0  = blockIdx.x * 128;
    int qi  = bq / 5;
    int pi  = (bq / 100)*5 + (bq % 5);

    uint32_t sbase = smem_u32(ds);

    for (int i = tid; i < 5*128; i += 256){
        int s = i >> 7, c = i & 127;
        s_pwr[i] = g_pw2[((size_t)pi*5 + s)*DD + n0 + c];
    }
    for (int i = tid; i < 640; i += 256) s_P[i] = g_P[(size_t)bq*640 + i];
    if (tid < 128){ s_qm[tid] = q_mask[qi*128 + tid]; s_bias[tid] = proj_b[n0 + tid]; }

    const char* gAh = (const char*)g_Ahi + (size_t)bq*128*3072;
    const char* gAl = (const char*)g_Alo + (size_t)bq*128*3072;
    const char* gBh = (const char*)g_Wh + (size_t)n0*6144 + 3072;   // cols 1536..3071
    const char* gBl = (const char*)g_Wl + (size_t)n0*6144 + 3072;

    float acc[4][4][4];
    #pragma unroll
    for (int a=0;a<4;a++)
        #pragma unroll
        for (int b=0;b<4;b++)
            #pragma unroll
            for (int r=0;r<4;r++) acc[a][b][r] = 0.f;

    int r0 = tid >> 2, k80 = tid & 3;
    int r1 = r0 + 64;
    uint32_t d0 = tile_off(r0, k80);
    uint32_t d1 = tile_off(r1, k80);

    auto issue = [&](int c, int buf){
        size_t koff = (size_t)c*64 + (size_t)k80*16;   // FIX: per-thread k-unit offset
        uint32_t sb = sbase + buf*STGSZ;
        size_t sa0 = (size_t)r0*3072 + koff;
        size_t sa1 = (size_t)r1*3072 + koff;
        size_t sb0 = (size_t)r0*6144 + koff;
        size_t sb1 = (size_t)r1*6144 + koff;
        cp16(sb + d0,          gAh + sa0);  cp16(sb + d1,          gAh + sa1);
        cp16(sb + TBUF + d0,   gAl + sa0);  cp16(sb + TBUF + d1,   gAl + sa1);
        cp16(sb + 2*TBUF + d0, gBh + sb0);  cp16(sb + 2*TBUF + d1, gBh + sb1);
        cp16(sb + 3*TBUF + d0, gBl + sb0);  cp16(sb + 3*TBUF + d1, gBl + sb1);
        cp_commit();
    };

    issue(0, 0);
    issue(1, 1);

    int a_m  = (lane & 15);
    int a_k8 = (lane >> 4);
    int b_n  = (lane & 7) + ((lane >> 4) << 3);
    int b_k8 = (lane >> 3) & 1;

    for (int c = 0; c < NCCH; c++){
        if (c + 2 < NCCH){ issue(c+2, (c+2)%3); cp_waitg<2>(); }
        else if (c + 1 < NCCH) cp_waitg<1>();
        else cp_waitg<0>();
        __syncthreads();
        uint32_t ah = sbase + (c%3)*STGSZ;
        uint32_t al = ah + TBUF;
        uint32_t bh = ah + 2*TBUF;
        uint32_t bl = ah + 3*TBUF;
        #pragma unroll
        for (int ks = 0; ks < 2; ks++){
            int ks8 = ks*2;
            uint32_t Ahf[4][4], Alf[4][4], Bhf[2][4], Blf[2][4];
            #pragma unroll
            for (int mt=0; mt<4; mt++){
                int m = wm*64 + mt*16 + a_m;
                uint32_t off = tile_off(m, ks8 + a_k8);
                ldsm4(ah + off, Ahf[mt]);
                ldsm4(al + off, Alf[mt]);
            }
            #pragma unroll
            for (int p=0; p<2; p++){
                int n = wn*32 + p*16 + b_n;
                uint32_t off = tile_off(n, ks8 + b_k8);
                ldsm4(bh + off, Bhf[p]);
                ldsm4(bl + off, Blf[p]);
            }
            #pragma unroll
            for (int mt=0; mt<4; mt++)
                #pragma unroll
                for (int nt=0; nt<4; nt++)
                    mma16816(acc[mt][nt], Ahf[mt], &Bhf[nt>>1][(nt&1)*2]);
            #pragma unroll
            for (int mt=0; mt<4; mt++)
                #pragma unroll
                for (int nt=0; nt<4; nt++)
                    mma16816(acc[mt][nt], Ahf[mt], &Blf[nt>>1][(nt&1)*2]);
            #pragma unroll
            for (int mt=0; mt<4; mt++)
                #pragma unroll
                for (int nt=0; nt<4; nt++)
                    mma16816(acc[mt][nt], Alf[mt], &Bhf[nt>>1][(nt&1)*2]);
        }
        __syncthreads();
    }

    // ---- fused epilogue ----
    float* vbuf = (float*)ds;   // [128 q][VSTRIDE]
    int row = lane >> 2, colb = (lane & 3)*2;
    #pragma unroll
    for (int mt=0; mt<4; mt++){
        #pragma unroll
        for (int h2=0; h2<2; h2++){
            int q = wm*64 + mt*16 + row + h2*8;
            float qm = s_qm[q];
            float p0=s_P[q*5+0], p1=s_P[q*5+1], p2=s_P[q*5+2], p3=s_P[q*5+3], p4=s_P[q*5+4];
            const float* t1row = g_T1 + ((size_t)qi*128 + q)*DD + n0;
            #pragma unroll
            for (int nt=0; nt<4; nt++){
                int cl = wn*32 + nt*8 + colb;
                float2 t1 = *(const float2*)(t1row + cl);
                float t2a = qm*(p0*s_pwr[cl] + p1*s_pwr[128+cl] + p2*s_pwr[256+cl]
                              + p3*s_pwr[384+cl] + p4*s_pwr[512+cl]);
                float t2b = qm*(p0*s_pwr[cl+1] + p1*s_pwr[128+cl+1] + p2*s_pwr[256+cl+1]
                              + p3*s_pwr[384+cl+1] + p4*s_pwr[512+cl+1]);
                float v0 = fmaxf(acc[mt][nt][h2*2+0] + t1.x + t2a + s_bias[cl], 0.f);
                float v1 = fmaxf(acc[mt][nt][h2*2+1] + t1.y + t2b + s_bias[cl+1], 0.f);
                vbuf[q*VSTRIDE + cl]     = v0;
                vbuf[q*VSTRIDE + cl + 1] = v1;
            }
        }
    }
    __syncthreads();
    if (tid < 128){
        float mx = 0.f, sm = 0.f;
        #pragma unroll 8
        for (int qq = 0; qq < 128; qq++){
            float v = vbuf[qq*VSTRIDE + tid];
            mx = fmaxf(mx, v); sm += v;
        }
        g_eqmax[(size_t)bq*DD + n0 + tid] = mx;
        g_eqsum[(size_t)bq*DD + n0 + tid] = sm;
    }
}

// ---------------- cat assembly (es reduce + eq agg) -> bf16 hi/lo ----------------
__global__ void cat_kernel(const float* __restrict__ q_mask)
{
    int bq = blockIdx.x, tid = threadIdx.x;
    int qi = bq / 5;
    __shared__ float sc[8];
    __shared__ float qs_s;
    float v = (tid < 128) ? q_mask[qi*128 + tid] : 0.f;
    float ws = warpSum(v);
    if ((tid&31)==0) sc[tid>>5] = ws;
    __syncthreads();
    if (tid == 0){
        float q = 0.f;
        #pragma unroll
        for (int r=0;r<8;r++) q += sc[r];
        qs_s = q;
    }
    __syncthreads();
    float qs = qs_s;
    #pragma unroll
    for (int j=0;j<3;j++){
        int d = tid + j*256;
        float mx = 0.f, sm = 0.f;
        #pragma unroll
        for (int s=0;s<TAGS;s++){
            float e = g_es[((size_t)(bq*TAGS + s))*DD + d];
            mx = fmaxf(mx, e); sm += e;
        }
        float f[4] = { g_eqmax[(size_t)bq*DD + d],
                       g_eqsum[(size_t)bq*DD + d] / qs,
                       mx, sm * 0.2f };
        size_t b = (size_t)bq*FD;
        #pragma unroll
        for (int cchunk=0;cchunk<4;cchunk++){
            float val = f[cchunk];
            __nv_bfloat16 hh = __float2bfloat16(val);
            g_Ch[b + cchunk*DD + d] = hh;
            g_Cl[b + cchunk*DD + d] = __float2bfloat16(val - __bfloat162float(hh));
        }
    }
}

// ---------------- final logits ----------------
__global__ void logits_kernel(const float* __restrict__ rel_w2,
                              const float* __restrict__ rel_b2,
                              float* __restrict__ out)
{
    int g = blockIdx.x*8 + (threadIdx.x >> 5);
    if (g >= BQC) return;
    int lane = threadIdx.x & 31;
    float s = 0.f;
    for (int d=lane; d<DD; d+=32) s += rel_w2[d]*g_h[(size_t)g*DD + d];
    s = warpSum(s);
    if (!lane) out[g] = s + rel_b2[0];
}

// ---------------- launcher ----------------
extern "C" void kernel_launch(void* const* d_in, const int* in_sizes, int n_in,
                              void* d_out, int out_size)
{
    const float* s_emb   = (const float*)d_in[0];
    const float* q_emb   = (const float*)d_in[1];
    const float* s_mask  = (const float*)d_in[2];
    const float* q_mask  = (const float*)d_in[3];
    const float* s_label = (const float*)d_in[4];
    const float* proj_w  = (const float*)d_in[5];
    const float* proj_b  = (const float*)d_in[6];
    const float* rel_w1  = (const float*)d_in[7];
    const float* rel_b1  = (const float*)d_in[8];
    const float* rel_w2  = (const float*)d_in[9];
    const float* rel_b2  = (const float*)d_in[10];
    float* out = (float*)d_out;

    __nv_bfloat16 *pWh, *pWl, *pRWh, *pRWl, *pQh, *pQl, *pFSh, *pFSl, *pCh, *pCl;
    cudaGetSymbolAddress((void**)&pWh,  g_Wh);  cudaGetSymbolAddress((void**)&pWl,  g_Wl);
    cudaGetSymbolAddress((void**)&pRWh, g_RWh); cudaGetSymbolAddress((void**)&pRWl, g_RWl);
    cudaGetSymbolAddress((void**)&pQh,  g_Qh);  cudaGetSymbolAddress((void**)&pQl,  g_Ql);
    cudaGetSymbolAddress((void**)&pFSh, g_FSh); cudaGetSymbolAddress((void**)&pFSl, g_FSl);
    cudaGetSymbolAddress((void**)&pCh,  g_Ch);  cudaGetSymbolAddress((void**)&pCl,  g_Cl);
    float *pT1, *pes, *ph;
    cudaGetSymbolAddress((void**)&pT1, g_T1);
    cudaGetSymbolAddress((void**)&pes, g_es);
    cudaGetSymbolAddress((void**)&ph,  g_h);

    static bool attr_set = false;
    if (!attr_set){
        cudaFuncSetAttribute(big_mma, cudaFuncAttributeMaxDynamicSharedMemorySize, 3*STGSZ);
        cudaFuncSetAttribute(hgemm<768,5120,false>, cudaFuncAttributeMaxDynamicSharedMemorySize, 3*STGSZ);
        cudaFuncSetAttribute(hgemm<3072,1000,true>, cudaFuncAttributeMaxDynamicSharedMemorySize, 3*STGSZ);
        cudaFuncSetAttribute(hgemm<3072,200,true>,  cudaFuncAttributeMaxDynamicSharedMemorySize, 3*STGSZ);
        cudaFuncSetAttribute(att_kernel, cudaFuncAttributeMaxDynamicSharedMemorySize, 25*DD*4);
        attr_set = true;
    }

    proto_kernel    <<<BNKC, 256>>>(s_emb, s_mask, s_label);
    proto_avg_kernel<<<150, 256>>>();
    split_kernel    <<<(DD*FD + 255)/256, 256>>>(proj_w, pWh, pWl, DD*FD);
    split_kernel    <<<(DD*FD + 255)/256, 256>>>(rel_w1, pRWh, pRWl, DD*FD);
    split_kernel    <<<(BNQ*LQ*DD + 255)/256, 256>>>(q_emb, pQh, pQl, BNQ*LQ*DD);
    pw2_gemm        <<<12, 256>>>(proj_w + DD);
    att_kernel      <<<BNQ, 256, 25*DD*4>>>(q_emb, q_mask);
    softq_kernel    <<<100, 256>>>();
    supp_kernel     <<<BQC, 256>>>(q_emb);
    aprime_kernel   <<<BQC, 256>>>(q_emb, q_mask);
    hgemm<768,5120,false><<<dim3(6,40), 256, 3*STGSZ>>>(pQh, pQl, pWh, pWl, pT1, nullptr);
    big_mma         <<<dim3(6, 200), 256, 3*STGSZ>>>(q_mask, proj_b);
    hgemm<3072,1000,true><<<dim3(6,8), 256, 3*STGSZ>>>(pFSh, pFSl, pWh, pWl, pes, proj_b);
    cat_kernel      <<<BQC, 256>>>(q_mask);
    hgemm<3072,200,true><<<dim3(6,2), 256, 3*STGSZ>>>(pCh, pCl, pRWh, pRWl, ph, rel_b1);
    logits_kernel   <<<25, 256>>>(rel_w2, rel_b2, out);
}

// round 6
// speedup vs baseline: 2.4716x; 1.1208x over previous
#include <cuda_runtime.h>
#include <cuda_bf16.h>
#include <math.h>
#include <stdint.h>

// Problem constants (fixed by setup_inputs)
#define DD    768
#define TAGS  5
#define LQ    128
#define BQC   200      // B*N*Q*N
#define BNQ   40       // B*N*Q
#define BNKC  50       // B*N*K
#define NPROT 10       // B*N
#define FD    3072     // 4*D
#define MBIG  25600    // BQC*LQ

// ---------------- scratch (device globals) --------------
__device__ float g_protok[BNKC*TAGS*DD];
__device__ float g_proto [NPROT*TAGS*DD];
__device__ float g_pw2   [NPROT*TAGS*DD];
__device__ float g_att   [BQC*TAGS*LQ];
__device__ float g_P     [BQC*LQ*TAGS];
__device__ __nv_bfloat16 g_Ahi[(size_t)MBIG*1536];
__device__ __nv_bfloat16 g_Alo[(size_t)MBIG*1536];
__device__ __nv_bfloat16 g_Wh [(size_t)DD*FD];      // proj_w split
__device__ __nv_bfloat16 g_Wl [(size_t)DD*FD];
__device__ __nv_bfloat16 g_RWh[(size_t)DD*FD];      // rel_w1 split
__device__ __nv_bfloat16 g_RWl[(size_t)DD*FD];
__device__ __nv_bfloat16 g_Qh [(size_t)BNQ*LQ*DD];  // q_emb split
__device__ __nv_bfloat16 g_Ql [(size_t)BNQ*LQ*DD];
__device__ __nv_bfloat16 g_FSh[(size_t)1024*FD];    // fuse-support rows (padded 1000->1024)
__device__ __nv_bfloat16 g_FSl[(size_t)1024*FD];
__device__ __nv_bfloat16 g_Ch [(size_t)256*FD];     // cat rows (padded 200->256)
__device__ __nv_bfloat16 g_Cl [(size_t)256*FD];
__device__ float g_T1    [BNQ*LQ*DD];
__device__ float g_es    [BQC*TAGS*DD];
__device__ float g_eqmax [BQC*DD];
__device__ float g_eqsum [BQC*DD];
__device__ float g_h     [BQC*DD];

__device__ __forceinline__ float warpMax(float v){
    #pragma unroll
    for (int o=16;o;o>>=1) v = fmaxf(v, __shfl_xor_sync(0xffffffffu, v, o));
    return v;
}
__device__ __forceinline__ float warpSum(float v){
    #pragma unroll
    for (int o=16;o;o>>=1) v += __shfl_xor_sync(0xffffffffu, v, o);
    return v;
}

// ================= HMMA helpers (baseline PTX) ====
__device__ __forceinline__ uint32_t smem_u32(const void* p) {
    uint32_t a;
    asm("{ .reg .u64 t; cvta.to.shared.u64 t, %1; cvt.u32.u64 %0, t; }" : "=r"(a) : "l"(p));
    return a;
}
__device__ __forceinline__ void cp16(uint32_t dst, const void* src){
    asm volatile("cp.async.cg.shared.global [%0], [%1], 16;" :: "r"(dst), "l"(src) : "memory");
}
__device__ __forceinline__ void cp_commit(){ asm volatile("cp.async.commit_group;" ::: "memory"); }
template<int N> __device__ __forceinline__ void cp_waitg(){
    asm volatile("cp.async.wait_group %0;" :: "n"(N) : "memory");
}
__device__ __forceinline__ void ldsm4(uint32_t a, uint32_t* r){
    asm volatile("ldmatrix.sync.aligned.m8n8.x4.shared.b16 {%0,%1,%2,%3}, [%4];"
        : "=r"(r[0]),"=r"(r[1]),"=r"(r[2]),"=r"(r[3]) : "r"(a));
}
__device__ __forceinline__ void mma16816(float* c, const uint32_t* a, const uint32_t* b){
    asm volatile("mma.sync.aligned.m16n8k16.row.col.f32.bf16.bf16.f32 "
        "{%0,%1,%2,%3},{%4,%5,%6,%7},{%8,%9},{%0,%1,%2,%3};"
        : "+f"(c[0]),"+f"(c[1]),"+f"(c[2]),"+f"(c[3])
        : "r"(a[0]),"r"(a[1]),"r"(a[2]),"r"(a[3]), "r"(b[0]),"r"(b[1]));
}
// SMEM tile swizzle for 128x32 bf16 tiles (rows of 64B = 4 x 16B units)
__device__ __forceinline__ uint32_t tile_off(int m, int k8){
    return (uint32_t)((m*4 + (k8 ^ ((m>>1)&3))) << 4);
}

// ---------------- K1: per-(b,n,k) tag prototypes ----------------
__global__ void proto_kernel(const float* __restrict__ s_emb,
                             const float* __restrict__ s_mask,
                             const float* __restrict__ s_label)
{
    int bnk = blockIdx.x, tid = threadIdx.x;
    __shared__ int   tags[128];
    __shared__ float wts[128];
    __shared__ float cnt[TAGS];
    if (tid < 128) {
        const float* lr = s_label + ((size_t)bnk*128 + tid)*TAGS;
        float best = lr[0]; int bi = 0;
        #pragma unroll
        for (int s=1;s<TAGS;s++){ float v = lr[s]; if (v > best){ best = v; bi = s; } }
        tags[tid] = bi;
        wts[tid]  = (bi == 0) ? s_mask[bnk*128 + tid] : 1.0f;
    }
    __syncthreads();
    if (tid < TAGS) {
        float c = 0.f;
        for (int t=0;t<128;t++) if (tags[t] == tid) c += wts[t];
        cnt[tid] = c;
    }
    __syncthreads();
    float acc[TAGS][3];
    #pragma unroll
    for (int k=0;k<TAGS;k++)
        #pragma unroll
        for (int j=0;j<3;j++) acc[k][j] = 0.f;
    const float* eb = s_emb + (size_t)bnk*128*DD;
    for (int t=0;t<128;t++){
        int tg = tags[t]; float w = wts[t];
        #pragma unroll
        for (int j=0;j<3;j++){
            float e = eb[t*DD + tid + j*256];
            #pragma unroll
            for (int k=0;k<TAGS;k++)
                acc[k][j] += ((tg == k) ? w : 0.0f) * e;
        }
    }
    #pragma unroll
    for (int k=0;k<TAGS;k++){
        float c = cnt[k];
        float inv = (c > 0.f) ? (1.0f / fmaxf(c, 1.0f)) : 0.0f;
        #pragma unroll
        for (int j=0;j<3;j++){
            int d = tid + j*256;
            g_protok[((size_t)bnk*TAGS + k)*DD + d] = (c > 0.f) ? acc[k][j]*inv : 0.0f;
        }
    }
}

// ---------------- K2: mean over K shots ----------------
__global__ void proto_avg_kernel()
{
    int i = blockIdx.x*256 + threadIdx.x;
    int pi = i / (TAGS*DD), rem = i % (TAGS*DD);
    float s = 0.f;
    #pragma unroll
    for (int k=0;k<5;k++) s += g_protok[((size_t)(pi*5 + k))*(TAGS*DD) + rem];
    g_proto[i] = s * 0.2f;
}

// ---------------- generic bf16 hi/lo split ----------------
__global__ void split_kernel(const float* __restrict__ src,
                             __nv_bfloat16* __restrict__ h,
                             __nv_bfloat16* __restrict__ l, int n)
{
    int i = blockIdx.x*256 + threadIdx.x;
    if (i >= n) return;
    float v = src[i];
    __nv_bfloat16 hh = __float2bfloat16(v);
    h[i] = hh;
    l[i] = __float2bfloat16(v - __bfloat162float(hh));
}

// ---------------- pw2 = proto @ W2^T (M=50, N=768, K=768), tiled SIMT ----------------
__global__ void __launch_bounds__(256) pw2_gemm(const float* __restrict__ Bw)  // Bw = proj_w + 768
{
    __shared__ float As[16][52];
    __shared__ float Bs[16][68];
    int tid = threadIdx.x;
    int tx = tid & 15, ty = tid >> 4;
    int n0 = blockIdx.x * 64;
    float acc[4][4];
    #pragma unroll
    for (int i=0;i<4;i++)
        #pragma unroll
        for (int j=0;j<4;j++) acc[i][j] = 0.f;
    int lm = tid >> 2, lk4 = (tid & 3)*4;
    for (int kt = 0; kt < 48; kt++){
        int kg = kt*16 + lk4;
        float4 a0 = (lm < 50) ? *(const float4*)(g_proto + (size_t)lm*DD + kg) : make_float4(0,0,0,0);
        float4 b0 = *(const float4*)(Bw + (size_t)(n0 + lm)*FD + kg);
        __syncthreads();
        if (lm < 50){
            As[lk4+0][lm]=a0.x; As[lk4+1][lm]=a0.y; As[lk4+2][lm]=a0.z; As[lk4+3][lm]=a0.w;
        }
        Bs[lk4+0][lm]=b0.x; Bs[lk4+1][lm]=b0.y; Bs[lk4+2][lm]=b0.z; Bs[lk4+3][lm]=b0.w;
        __syncthreads();
        if (ty < 13){
            #pragma unroll
            for (int kk=0;kk<16;kk++){
                float a[4], b[4];
                #pragma unroll
                for (int i=0;i<4;i++) a[i] = (ty*4+i < 50) ? As[kk][ty*4+i] : 0.f;
                float4 bv = *(const float4*)&Bs[kk][tx*4];
                b[0]=bv.x; b[1]=bv.y; b[2]=bv.z; b[3]=bv.w;
                #pragma unroll
                for (int i=0;i<4;i++)
                    #pragma unroll
                    for (int j=0;j<4;j++) acc[i][j] += a[i]*b[j];
            }
        }
    }
    #pragma unroll
    for (int i=0;i<4;i++){
        int gm = ty*4 + i;
        if (gm < 50){
            #pragma unroll
            for (int j=0;j<4;j++)
                g_pw2[(size_t)gm*DD + n0 + tx*4 + j] = acc[i][j];
        }
    }
}

// ---------------- attention scores: block per qi ----------------
__global__ void __launch_bounds__(256) att_kernel(const float* __restrict__ q_emb,
                                                  const float* __restrict__ q_mask)
{
    extern __shared__ float sp[];        // 25 proto rows x 768
    int qi = blockIdx.x, tid = threadIdx.x;
    int b = qi / 20;
    const float* pb = g_proto + (size_t)b*25*DD;
    for (int i = tid; i < 25*DD; i += 256) sp[i] = pb[i];
    __syncthreads();
    int wid = tid >> 5, lane = tid & 31;
    const float4* sp4 = (const float4*)sp;
    for (int r = wid; r < 128; r += 8){
        const float4* qr4 = (const float4*)(q_emb + ((size_t)qi*128 + r)*DD);
        float acc[25];
        #pragma unroll
        for (int t=0;t<25;t++) acc[t] = 0.f;
        for (int d4 = lane; d4 < 192; d4 += 32){
            float4 qv = qr4[d4];
            #pragma unroll
            for (int t=0;t<25;t++){
                float4 sv = sp4[t*192 + d4];
                acc[t] += qv.x*sv.x + qv.y*sv.y + qv.z*sv.z + qv.w*sv.w;
            }
        }
        float qmb = q_mask[qi*128 + r]*100.0f;
        #pragma unroll
        for (int t=0;t<25;t++){
            float s = warpSum(acc[t]);
            if (lane == (t & 31)){
                int c = t / 5, sg = t % 5;
                g_att[(size_t)(qi*5 + c)*640 + sg*128 + r] = s + qmb;
            }
        }
    }
}

// ---------------- softmax over s (5 values) ----------------
__global__ void softq_kernel()
{
    int t = blockIdx.x*256 + threadIdx.x;
    int bq = t >> 7, q = t & 127;
    float v[TAGS];
    float mx = -3.4e38f;
    #pragma unroll
    for (int s=0;s<TAGS;s++){ v[s] = g_att[(size_t)bq*640 + s*128 + q]; mx = fmaxf(mx, v[s]); }
    float sm = 0.f;
    #pragma unroll
    for (int s=0;s<TAGS;s++){ v[s] = expf(v[s]-mx); sm += v[s]; }
    float inv = 1.0f/sm;
    #pragma unroll
    for (int s=0;s<TAGS;s++) g_P[(size_t)bq*640 + q*5 + s] = v[s]*inv;
}

// ---------------- support_ + fuse rows (writes bf16 hi/lo) ----------------
__global__ void supp_kernel(const float* __restrict__ q_emb)
{
    int bq = blockIdx.x, tid = threadIdx.x;
    int qi = bq / 5;
    int pi = (bq / 100)*5 + (bq % 5);
    __shared__ float arow[TAGS][128];
    __shared__ float ps[TAGS][DD];
    __shared__ float sc[8];
    for (int i=tid;i<TAGS*128;i+=256) arow[i>>7][i&127] = g_att[(size_t)bq*640 + i];
    for (int i=tid;i<TAGS*DD;i+=256) (&ps[0][0])[i] = g_proto[(size_t)pi*TAGS*DD + i];
    __syncthreads();
    for (int s=0;s<TAGS;s++){
        float v = (tid<128) ? arow[s][tid] : -3.4e38f;
        float wm = warpMax(v);
        if ((tid&31)==0) sc[tid>>5] = wm;
        __syncthreads();
        float bm = sc[0];
        #pragma unroll
        for (int r=1;r<8;r++) bm = fmaxf(bm, sc[r]);
        float e = (tid<128) ? expf(v-bm) : 0.f;
        float wsm = warpSum(e);
        __syncthreads();
        if ((tid&31)==0) sc[tid>>5] = wsm;
        __syncthreads();
        float bs = sc[0];
        #pragma unroll
        for (int r=1;r<8;r++) bs += sc[r];
        if (tid<128) arow[s][tid] = e / bs;
        __syncthreads();
    }
    float acc[TAGS][3];
    #pragma unroll
    for (int s=0;s<TAGS;s++)
        #pragma unroll
        for (int j=0;j<3;j++) acc[s][j] = 0.f;
    const float* qb = q_emb + (size_t)qi*128*DD;
    for (int q=0;q<128;q++){
        float w0=arow[0][q], w1=arow[1][q], w2=arow[2][q], w3=arow[3][q], w4=arow[4][q];
        #pragma unroll
        for (int j=0;j<3;j++){
            float e = qb[q*DD + tid + j*256];
            acc[0][j]+=w0*e; acc[1][j]+=w1*e; acc[2][j]+=w2*e; acc[3][j]+=w3*e; acc[4][j]+=w4*e;
        }
    }
    #pragma unroll
    for (int j=0;j<3;j++){
        int d = tid + j*256;
        #pragma unroll
        for (int s=0;s<TAGS;s++){
            float m1 = ps[s][d];
            float m2 = acc[s][j];
            float f[4] = { m1, m2, fabsf(m1-m2), m1*m2 };
            size_t base = ((size_t)(bq*TAGS + s))*FD;
            #pragma unroll
            for (int cchunk=0;cchunk<4;cchunk++){
                float v = f[cchunk];
                __nv_bfloat16 hh = __float2bfloat16(v);
                g_FSh[base + cchunk*DD + d] = hh;
                g_FSl[base + cchunk*DD + d] = __float2bfloat16(v - __bfloat162float(hh));
            }
        }
    }
}

// ---------------- query-side feature rows -> bf16 hi/lo (grid 200 x 4) ----------------
__global__ void aprime_kernel(const float* __restrict__ q_emb,
                              const float* __restrict__ q_mask)
{
    int bq = blockIdx.x, tid = threadIdx.x;
    int q0 = blockIdx.y * 32;
    int qi = bq / 5;
    int pi = (bq / 100)*5 + (bq % 5);
    __shared__ float ps[TAGS*DD];
    __shared__ float sP[640];
    __shared__ float sqm[128];
    for (int i=tid;i<TAGS*DD;i+=256) ps[i] = g_proto[(size_t)pi*TAGS*DD + i];
    for (int i=tid;i<640;i+=256) sP[i] = g_P[(size_t)bq*640 + i];
    if (tid < 128) sqm[tid] = q_mask[qi*128 + tid];
    __syncthreads();
    for (int q = q0; q < q0 + 32; q++){
        float p0=sP[q*5+0], p1=sP[q*5+1], p2=sP[q*5+2], p3=sP[q*5+3], p4=sP[q*5+4];
        float qm = sqm[q];
        const float* qr = q_emb + ((size_t)qi*128 + q)*DD;
        size_t base = ((size_t)bq*128 + q)*1536;
        for (int d = tid; d < DD; d += 256){
            float m2 = qm * (p0*ps[d] + p1*ps[DD+d] + p2*ps[2*DD+d] + p3*ps[3*DD+d] + p4*ps[4*DD+d]);
            float m1 = qr[d];
            float va = fabsf(m1 - m2);
            float vp = m1*m2;
            __nv_bfloat16 ah = __float2bfloat16(va);
            __nv_bfloat16 al = __float2bfloat16(va - __bfloat162float(ah));
            __nv_bfloat16 ph = __float2bfloat16(vp);
            __nv_bfloat16 pl = __float2bfloat16(vp - __bfloat162float(ph));
            g_Ahi[base + d]      = ah;  g_Alo[base + d]      = al;
            g_Ahi[base + DD + d] = ph;  g_Alo[base + DD + d] = pl;
        }
    }
}

// ================= generic HMMA GEMM: C = [relu](A @ B^T [+ bias]) =========
// 2-stage cp.async double buffer, 2 CTAs/SM.
#define TBUF  8192
#define STGSZ (4*TBUF)

template<int KDIM, int MDIM, bool RELU>
__global__ void __launch_bounds__(256,2) hgemm(const __nv_bfloat16* __restrict__ Ah_,
                                               const __nv_bfloat16* __restrict__ Al_,
                                               const __nv_bfloat16* __restrict__ Bh_,
                                               const __nv_bfloat16* __restrict__ Bl_,
                                               float* __restrict__ C,
                                               const float* __restrict__ bias)
{
    constexpr int NC = KDIM / 32;
    extern __shared__ __align__(128) char ds[];
    int tid = threadIdx.x;
    int lane = tid & 31, wid = tid >> 5;
    int wm = wid & 1, wn = wid >> 1;
    int m0 = blockIdx.y * 128, n0 = blockIdx.x * 128;
    uint32_t sbase = smem_u32(ds);

    const char* gAh = (const char*)Ah_ + (size_t)m0*KDIM*2;
    const char* gAl = (const char*)Al_ + (size_t)m0*KDIM*2;
    const char* gBh = (const char*)Bh_ + (size_t)n0*FD*2;
    const char* gBl = (const char*)Bl_ + (size_t)n0*FD*2;

    float acc[4][4][4];
    #pragma unroll
    for (int a=0;a<4;a++)
        #pragma unroll
        for (int b=0;b<4;b++)
            #pragma unroll
            for (int r=0;r<4;r++) acc[a][b][r] = 0.f;

    int r0 = tid >> 2, k80 = tid & 3;
    int r1 = r0 + 64;
    uint32_t d0 = tile_off(r0, k80);
    uint32_t d1 = tile_off(r1, k80);

    auto issue = [&](int c){
        size_t koff = (size_t)c*64 + (size_t)k80*16;
        uint32_t sb = sbase + (c & 1)*STGSZ;
        size_t sa0 = (size_t)r0*(KDIM*2) + koff;
        size_t sa1 = (size_t)r1*(KDIM*2) + koff;
        size_t sb0 = (size_t)r0*(FD*2) + koff;
        size_t sb1 = (size_t)r1*(FD*2) + koff;
        cp16(sb + d0,          gAh + sa0);  cp16(sb + d1,          gAh + sa1);
        cp16(sb + TBUF + d0,   gAl + sa0);  cp16(sb + TBUF + d1,   gAl + sa1);
        cp16(sb + 2*TBUF + d0, gBh + sb0);  cp16(sb + 2*TBUF + d1, gBh + sb1);
        cp16(sb + 3*TBUF + d0, gBl + sb0);  cp16(sb + 3*TBUF + d1, gBl + sb1);
        cp_commit();
    };

    issue(0);
    issue(1);

    int a_m  = (lane & 15);
    int a_k8 = (lane >> 4);
    int b_n  = (lane & 7) + ((lane >> 4) << 3);
    int b_k8 = (lane >> 3) & 1;

    for (int c = 0; c < NC; c++){
        if (c + 1 < NC) cp_waitg<1>(); else cp_waitg<0>();
        __syncthreads();
        uint32_t ah = sbase + (c & 1)*STGSZ;
        uint32_t al = ah + TBUF;
        uint32_t bh = ah + 2*TBUF;
        uint32_t bl = ah + 3*TBUF;
        #pragma unroll
        for (int ks = 0; ks < 2; ks++){
            int ks8 = ks*2;
            uint32_t Bhf[2][4], Blf[2][4], Af[4][4];
            #pragma unroll
            for (int p=0; p<2; p++){
                int n = wn*32 + p*16 + b_n;
                uint32_t off = tile_off(n, ks8 + b_k8);
                ldsm4(bh + off, Bhf[p]);
                ldsm4(bl + off, Blf[p]);
            }
            #pragma unroll
            for (int mt=0; mt<4; mt++){
                int m = wm*64 + mt*16 + a_m;
                ldsm4(ah + tile_off(m, ks8 + a_k8), Af[mt]);
            }
            #pragma unroll
            for (int mt=0; mt<4; mt++)
                #pragma unroll
                for (int nt=0; nt<4; nt++)
                    mma16816(acc[mt][nt], Af[mt], &Bhf[nt>>1][(nt&1)*2]);
            #pragma unroll
            for (int mt=0; mt<4; mt++)
                #pragma unroll
                for (int nt=0; nt<4; nt++)
                    mma16816(acc[mt][nt], Af[mt], &Blf[nt>>1][(nt&1)*2]);
            #pragma unroll
            for (int mt=0; mt<4; mt++){
                int m = wm*64 + mt*16 + a_m;
                ldsm4(al + tile_off(m, ks8 + a_k8), Af[mt]);
            }
            #pragma unroll
            for (int mt=0; mt<4; mt++)
                #pragma unroll
                for (int nt=0; nt<4; nt++)
                    mma16816(acc[mt][nt], Af[mt], &Bhf[nt>>1][(nt&1)*2]);
        }
        __syncthreads();
        if (c + 2 < NC) issue(c+2);
    }

    int row = lane >> 2, colb = (lane & 3)*2;
    #pragma unroll
    for (int mt=0; mt<4; mt++){
        #pragma unroll
        for (int h2=0; h2<2; h2++){
            int gm = m0 + wm*64 + mt*16 + row + h2*8;
            if (gm < MDIM){
                #pragma unroll
                for (int nt=0; nt<4; nt++){
                    int cl = wn*32 + nt*8 + colb;
                    int gn = n0 + cl;
                    float v0 = acc[mt][nt][h2*2+0];
                    float v1 = acc[mt][nt][h2*2+1];
                    if (RELU){
                        v0 = fmaxf(v0 + bias[gn], 0.f);
                        v1 = fmaxf(v1 + bias[gn+1], 0.f);
                    }
                    C[(size_t)gm*DD + gn]   = v0;
                    C[(size_t)gm*DD + gn+1] = v1;
                }
            }
        }
    }
}

// ================= Big GEMM (hi/lo split, fused epilogue, shuffle reduce) =========
#define NCCH  48

__global__ void __launch_bounds__(256,2) big_mma(const float* __restrict__ q_mask,
                                                 const float* __restrict__ proj_b)
{
    extern __shared__ __align__(128) char ds[];
    __shared__ float s_pwr[5*128];
    __shared__ float s_P[640];
    __shared__ float s_qm[128];
    __shared__ float s_bias[128];
    __shared__ float s_rmax[2][128];
    __shared__ float s_rsum[2][128];

    int tid = threadIdx.x;
    int lane = tid & 31, wid = tid >> 5;
    int wm = wid & 1;
    int wn = wid >> 1;
    int bq  = blockIdx.y;
    int n0  = blockIdx.x * 128;
    int qi  = bq / 5;
    int pi  = (bq / 100)*5 + (bq % 5);

    uint32_t sbase = smem_u32(ds);

    for (int i = tid; i < 5*128; i += 256){
        int s = i >> 7, c = i & 127;
        s_pwr[i] = g_pw2[((size_t)pi*5 + s)*DD + n0 + c];
    }
    for (int i = tid; i < 640; i += 256) s_P[i] = g_P[(size_t)bq*640 + i];
    if (tid < 128){ s_qm[tid] = q_mask[qi*128 + tid]; s_bias[tid] = proj_b[n0 + tid]; }

    const char* gAh = (const char*)g_Ahi + (size_t)bq*128*3072;
    const char* gAl = (const char*)g_Alo + (size_t)bq*128*3072;
    const char* gBh = (const char*)g_Wh + (size_t)n0*6144 + 3072;   // cols 1536..3071
    const char* gBl = (const char*)g_Wl + (size_t)n0*6144 + 3072;

    float acc[4][4][4];
    #pragma unroll
    for (int a=0;a<4;a++)
        #pragma unroll
        for (int b=0;b<4;b++)
            #pragma unroll
            for (int r=0;r<4;r++) acc[a][b][r] = 0.f;

    int r0 = tid >> 2, k80 = tid & 3;
    int r1 = r0 + 64;
    uint32_t d0 = tile_off(r0, k80);
    uint32_t d1 = tile_off(r1, k80);

    auto issue = [&](int c){
        size_t koff = (size_t)c*64 + (size_t)k80*16;
        uint32_t sb = sbase + (c & 1)*STGSZ;
        size_t sa0 = (size_t)r0*3072 + koff;
        size_t sa1 = (size_t)r1*3072 + koff;
        size_t sb0 = (size_t)r0*6144 + koff;
        size_t sb1 = (size_t)r1*6144 + koff;
        cp16(sb + d0,          gAh + sa0);  cp16(sb + d1,          gAh + sa1);
        cp16(sb + TBUF + d0,   gAl + sa0);  cp16(sb + TBUF + d1,   gAl + sa1);
        cp16(sb + 2*TBUF + d0, gBh + sb0);  cp16(sb + 2*TBUF + d1, gBh + sb1);
        cp16(sb + 3*TBUF + d0, gBl + sb0);  cp16(sb + 3*TBUF + d1, gBl + sb1);
        cp_commit();
    };

    issue(0);
    issue(1);

    int a_m  = (lane & 15);
    int a_k8 = (lane >> 4);
    int b_n  = (lane & 7) + ((lane >> 4) << 3);
    int b_k8 = (lane >> 3) & 1;

    for (int c = 0; c < NCCH; c++){
        if (c + 1 < NCCH) cp_waitg<1>(); else cp_waitg<0>();
        __syncthreads();
        uint32_t ah = sbase + (c & 1)*STGSZ;
        uint32_t al = ah + TBUF;
        uint32_t bh = ah + 2*TBUF;
        uint32_t bl = ah + 3*TBUF;
        #pragma unroll
        for (int ks = 0; ks < 2; ks++){
            int ks8 = ks*2;
            uint32_t Bhf[2][4], Blf[2][4], Af[4][4];
            #pragma unroll
            for (int p=0; p<2; p++){
                int n = wn*32 + p*16 + b_n;
                uint32_t off = tile_off(n, ks8 + b_k8);
                ldsm4(bh + off, Bhf[p]);
                ldsm4(bl + off, Blf[p]);
            }
            #pragma unroll
            for (int mt=0; mt<4; mt++){
                int m = wm*64 + mt*16 + a_m;
                ldsm4(ah + tile_off(m, ks8 + a_k8), Af[mt]);
            }
            #pragma unroll
            for (int mt=0; mt<4; mt++)
                #pragma unroll
                for (int nt=0; nt<4; nt++)
                    mma16816(acc[mt][nt], Af[mt], &Bhf[nt>>1][(nt&1)*2]);
            #pragma unroll
            for (int mt=0; mt<4; mt++)
                #pragma unroll
                for (int nt=0; nt<4; nt++)
                    mma16816(acc[mt][nt], Af[mt], &Blf[nt>>1][(nt&1)*2]);
            #pragma unroll
            for (int mt=0; mt<4; mt++){
                int m = wm*64 + mt*16 + a_m;
                ldsm4(al + tile_off(m, ks8 + a_k8), Af[mt]);
            }
            #pragma unroll
            for (int mt=0; mt<4; mt++)
                #pragma unroll
                for (int nt=0; nt<4; nt++)
                    mma16816(acc[mt][nt], Af[mt], &Bhf[nt>>1][(nt&1)*2]);
        }
        __syncthreads();
        if (c + 2 < NCCH) issue(c+2);
    }

    // ---- fused epilogue: +T1 +t2 +bias, relu, then max/sum over q via shuffles ----
    int row = lane >> 2, colb = (lane & 3)*2;
    float lmax[4][2], lsum[4][2];
    #pragma unroll
    for (int nt=0; nt<4; nt++)
        #pragma unroll
        for (int j=0;j<2;j++){ lmax[nt][j] = 0.f; lsum[nt][j] = 0.f; }

    #pragma unroll
    for (int mt=0; mt<4; mt++){
        #pragma unroll
        for (int h2=0; h2<2; h2++){
            int q = wm*64 + mt*16 + row + h2*8;
            float qm = s_qm[q];
            float p0=s_P[q*5+0], p1=s_P[q*5+1], p2=s_P[q*5+2], p3=s_P[q*5+3], p4=s_P[q*5+4];
            const float* t1row = g_T1 + ((size_t)qi*128 + q)*DD + n0;
            #pragma unroll
            for (int nt=0; nt<4; nt++){
                int cl = wn*32 + nt*8 + colb;
                float2 t1 = *(const float2*)(t1row + cl);
                float t2a = qm*(p0*s_pwr[cl] + p1*s_pwr[128+cl] + p2*s_pwr[256+cl]
                              + p3*s_pwr[384+cl] + p4*s_pwr[512+cl]);
                float t2b = qm*(p0*s_pwr[cl+1] + p1*s_pwr[128+cl+1] + p2*s_pwr[256+cl+1]
                              + p3*s_pwr[384+cl+1] + p4*s_pwr[512+cl+1]);
                float v0 = fmaxf(acc[mt][nt][h2*2+0] + t1.x + t2a + s_bias[cl], 0.f);
                float v1 = fmaxf(acc[mt][nt][h2*2+1] + t1.y + t2b + s_bias[cl+1], 0.f);
                lmax[nt][0] = fmaxf(lmax[nt][0], v0); lsum[nt][0] += v0;
                lmax[nt][1] = fmaxf(lmax[nt][1], v1); lsum[nt][1] += v1;
            }
        }
    }
    // reduce across row lanes (lane bits 2,3,4)
    #pragma unroll
    for (int o = 4; o <= 16; o <<= 1){
        #pragma unroll
        for (int nt=0; nt<4; nt++)
            #pragma unroll
            for (int j=0;j<2;j++){
                lmax[nt][j] = fmaxf(lmax[nt][j], __shfl_xor_sync(0xffffffffu, lmax[nt][j], o));
                lsum[nt][j] += __shfl_xor_sync(0xffffffffu, lsum[nt][j], o);
            }
    }
    if (row == 0){
        #pragma unroll
        for (int nt=0; nt<4; nt++){
            int cl = wn*32 + nt*8 + colb;
            s_rmax[wm][cl]   = lmax[nt][0];  s_rsum[wm][cl]   = lsum[nt][0];
            s_rmax[wm][cl+1] = lmax[nt][1];  s_rsum[wm][cl+1] = lsum[nt][1];
        }
    }
    __syncthreads();
    if (tid < 128){
        g_eqmax[(size_t)bq*DD + n0 + tid] = fmaxf(s_rmax[0][tid], s_rmax[1][tid]);
        g_eqsum[(size_t)bq*DD + n0 + tid] = s_rsum[0][tid] + s_rsum[1][tid];
    }
}

// ---------------- cat assembly (es reduce + eq agg) -> bf16 hi/lo ----------------
__global__ void cat_kernel(const float* __restrict__ q_mask)
{
    int bq = blockIdx.x, tid = threadIdx.x;
    int qi = bq / 5;
    __shared__ float sc[8];
    __shared__ float qs_s;
    float v = (tid < 128) ? q_mask[qi*128 + tid] : 0.f;
    float ws = warpSum(v);
    if ((tid&31)==0) sc[tid>>5] = ws;
    __syncthreads();
    if (tid == 0){
        float q = 0.f;
        #pragma unroll
        for (int r=0;r<8;r++) q += sc[r];
        qs_s = q;
    }
    __syncthreads();
    float qs = qs_s;
    #pragma unroll
    for (int j=0;j<3;j++){
        int d = tid + j*256;
        float mx = 0.f, sm = 0.f;
        #pragma unroll
        for (int s=0;s<TAGS;s++){
            float e = g_es[((size_t)(bq*TAGS + s))*DD + d];
            mx = fmaxf(mx, e); sm += e;
        }
        float f[4] = { g_eqmax[(size_t)bq*DD + d],
                       g_eqsum[(size_t)bq*DD + d] / qs,
                       mx, sm * 0.2f };
        size_t b = (size_t)bq*FD;
        #pragma unroll
        for (int cchunk=0;cchunk<4;cchunk++){
            float val = f[cchunk];
            __nv_bfloat16 hh = __float2bfloat16(val);
            g_Ch[b + cchunk*DD + d] = hh;
            g_Cl[b + cchunk*DD + d] = __float2bfloat16(val - __bfloat162float(hh));
        }
    }
}

// ---------------- final logits ----------------
__global__ void logits_kernel(const float* __restrict__ rel_w2,
                              const float* __restrict__ rel_b2,
                              float* __restrict__ out)
{
    int g = blockIdx.x*8 + (threadIdx.x >> 5);
    if (g >= BQC) return;
    int lane = threadIdx.x & 31;
    float s = 0.f;
    for (int d=lane; d<DD; d+=32) s += rel_w2[d]*g_h[(size_t)g*DD + d];
    s = warpSum(s);
    if (!lane) out[g] = s + rel_b2[0];
}

// ---------------- launcher ----------------
extern "C" void kernel_launch(void* const* d_in, const int* in_sizes, int n_in,
                              void* d_out, int out_size)
{
    const float* s_emb   = (const float*)d_in[0];
    const float* q_emb   = (const float*)d_in[1];
    const float* s_mask  = (const float*)d_in[2];
    const float* q_mask  = (const float*)d_in[3];
    const float* s_label = (const float*)d_in[4];
    const float* proj_w  = (const float*)d_in[5];
    const float* proj_b  = (const float*)d_in[6];
    const float* rel_w1  = (const float*)d_in[7];
    const float* rel_b1  = (const float*)d_in[8];
    const float* rel_w2  = (const float*)d_in[9];
    const float* rel_b2  = (const float*)d_in[10];
    float* out = (float*)d_out;

    __nv_bfloat16 *pWh, *pWl, *pRWh, *pRWl, *pQh, *pQl, *pFSh, *pFSl, *pCh, *pCl;
    cudaGetSymbolAddress((void**)&pWh,  g_Wh);  cudaGetSymbolAddress((void**)&pWl,  g_Wl);
    cudaGetSymbolAddress((void**)&pRWh, g_RWh); cudaGetSymbolAddress((void**)&pRWl, g_RWl);
    cudaGetSymbolAddress((void**)&pQh,  g_Qh);  cudaGetSymbolAddress((void**)&pQl,  g_Ql);
    cudaGetSymbolAddress((void**)&pFSh, g_FSh); cudaGetSymbolAddress((void**)&pFSl, g_FSl);
    cudaGetSymbolAddress((void**)&pCh,  g_Ch);  cudaGetSymbolAddress((void**)&pCl,  g_Cl);
    float *pT1, *pes, *ph;
    cudaGetSymbolAddress((void**)&pT1, g_T1);
    cudaGetSymbolAddress((void**)&pes, g_es);
    cudaGetSymbolAddress((void**)&ph,  g_h);

    static bool attr_set = false;
    if (!attr_set){
        cudaFuncSetAttribute(big_mma, cudaFuncAttributeMaxDynamicSharedMemorySize, 2*STGSZ);
        cudaFuncSetAttribute(hgemm<768,5120,false>, cudaFuncAttributeMaxDynamicSharedMemorySize, 2*STGSZ);
        cudaFuncSetAttribute(hgemm<3072,1000,true>, cudaFuncAttributeMaxDynamicSharedMemorySize, 2*STGSZ);
        cudaFuncSetAttribute(hgemm<3072,200,true>,  cudaFuncAttributeMaxDynamicSharedMemorySize, 2*STGSZ);
        cudaFuncSetAttribute(att_kernel, cudaFuncAttributeMaxDynamicSharedMemorySize, 25*DD*4);
        attr_set = true;
    }

    proto_kernel    <<<BNKC, 256>>>(s_emb, s_mask, s_label);
    proto_avg_kernel<<<150, 256>>>();
    split_kernel    <<<(DD*FD + 255)/256, 256>>>(proj_w, pWh, pWl, DD*FD);
    split_kernel    <<<(DD*FD + 255)/256, 256>>>(rel_w1, pRWh, pRWl, DD*FD);
    split_kernel    <<<(BNQ*LQ*DD + 255)/256, 256>>>(q_emb, pQh, pQl, BNQ*LQ*DD);
    pw2_gemm        <<<12, 256>>>(proj_w + DD);
    att_kernel      <<<BNQ, 256, 25*DD*4>>>(q_emb, q_mask);
    softq_kernel    <<<100, 256>>>();
    supp_kernel     <<<BQC, 256>>>(q_emb);
    aprime_kernel   <<<dim3(BQC,4), 256>>>(q_emb, q_mask);
    hgemm<768,5120,false><<<dim3(6,40), 256, 2*STGSZ>>>(pQh, pQl, pWh, pWl, pT1, nullptr);
    big_mma         <<<dim3(6, 200), 256, 2*STGSZ>>>(q_mask, proj_b);
    hgemm<3072,1000,true><<<dim3(6,8), 256, 2*STGSZ>>>(pFSh, pFSl, pWh, pWl, pes, proj_b);
    cat_kernel      <<<BQC, 256>>>(q_mask);
    hgemm<3072,200,true><<<dim3(6,2), 256, 2*STGSZ>>>(pCh, pCl, pRWh, pRWl, ph, rel_b1);
    logits_kernel   <<<25, 256>>>(rel_w2, rel_b2, out);
}

// round 7
// speedup vs baseline: 2.6228x; 1.0612x over previous
#include <cuda_runtime.h>
#include <cuda_bf16.h>
#include <math.h>
#include <stdint.h>

// Problem constants (fixed by setup_inputs)
#define DD    768
#define TAGS  5
#define LQ    128
#define BQC   200      // B*N*Q*N
#define BNQ   40       // B*N*Q
#define BNKC  50       // B*N*K
#define NPROT 10       // B*N
#define FD    3072     // 4*D
#define MBIG  25600    // BQC*LQ

// ---------------- scratch (device globals) --------------
__device__ float g_protok[BNKC*TAGS*DD];
__device__ float g_proto [NPROT*TAGS*DD];
__device__ float g_pw2   [NPROT*TAGS*DD];
__device__ float g_att   [BQC*TAGS*LQ];
__device__ float g_P     [BQC*LQ*TAGS];
__device__ __nv_bfloat16 g_Ahi[(size_t)MBIG*1536];
__device__ __nv_bfloat16 g_Alo[(size_t)MBIG*1536];
__device__ __nv_bfloat16 g_Wh [(size_t)DD*FD];      // proj_w split
__device__ __nv_bfloat16 g_Wl [(size_t)DD*FD];
__device__ __nv_bfloat16 g_RWh[(size_t)DD*FD];      // rel_w1 split
__device__ __nv_bfloat16 g_RWl[(size_t)DD*FD];
__device__ __nv_bfloat16 g_Qh [(size_t)BNQ*LQ*DD];  // q_emb split
__device__ __nv_bfloat16 g_Ql [(size_t)BNQ*LQ*DD];
__device__ __nv_bfloat16 g_FSh[(size_t)1024*FD];    // fuse-support rows (padded)
__device__ __nv_bfloat16 g_FSl[(size_t)1024*FD];
__device__ __nv_bfloat16 g_Ch [(size_t)256*FD];     // cat rows (padded)
__device__ __nv_bfloat16 g_Cl [(size_t)256*FD];
__device__ float g_T1    [BNQ*LQ*DD];
__device__ float g_es    [BQC*TAGS*DD];
__device__ float g_eqmax [BQC*DD];
__device__ float g_eqsum [BQC*DD];
__device__ float g_h     [BQC*DD];

__device__ __forceinline__ float warpMax(float v){
    #pragma unroll
    for (int o=16;o;o>>=1) v = fmaxf(v, __shfl_xor_sync(0xffffffffu, v, o));
    return v;
}
__device__ __forceinline__ float warpSum(float v){
    #pragma unroll
    for (int o=16;o;o>>=1) v += __shfl_xor_sync(0xffffffffu, v, o);
    return v;
}

// ================= HMMA helpers =================
__device__ __forceinline__ uint32_t smem_u32(const void* p) {
    uint32_t a;
    asm("{ .reg .u64 t; cvta.to.shared.u64 t, %1; cvt.u32.u64 %0, t; }" : "=r"(a) : "l"(p));
    return a;
}
__device__ __forceinline__ void cp16(uint32_t dst, const void* src){
    asm volatile("cp.async.cg.shared.global [%0], [%1], 16;" :: "r"(dst), "l"(src) : "memory");
}
__device__ __forceinline__ void cp_commit(){ asm volatile("cp.async.commit_group;" ::: "memory"); }
template<int N> __device__ __forceinline__ void cp_waitg(){
    asm volatile("cp.async.wait_group %0;" :: "n"(N) : "memory");
}
__device__ __forceinline__ void ldsm4(uint32_t a, uint32_t* r){
    asm volatile("ldmatrix.sync.aligned.m8n8.x4.shared.b16 {%0,%1,%2,%3}, [%4];"
        : "=r"(r[0]),"=r"(r[1]),"=r"(r[2]),"=r"(r[3]) : "r"(a));
}
__device__ __forceinline__ void mma16816(float* c, const uint32_t* a, const uint32_t* b){
    asm volatile("mma.sync.aligned.m16n8k16.row.col.f32.bf16.bf16.f32 "
        "{%0,%1,%2,%3},{%4,%5,%6,%7},{%8,%9},{%0,%1,%2,%3};"
        : "+f"(c[0]),"+f"(c[1]),"+f"(c[2]),"+f"(c[3])
        : "r"(a[0]),"r"(a[1]),"r"(a[2]),"r"(a[3]), "r"(b[0]),"r"(b[1]));
}
__device__ __forceinline__ uint32_t tile_off(int m, int k8){
    return (uint32_t)((m*4 + (k8 ^ ((m>>1)&3))) << 4);
}

#define TBUF  8192
#define STGSZ (4*TBUF)
#define DSMEM (3*STGSZ)

// ================= generic HMMA GEMM device core =================
// 3-stage cp.async pipeline, single __syncthreads per chunk.
template<int KDIM, int MDIM, bool RELU>
__device__ void dev_hgemm(int bx, int by,
                          const __nv_bfloat16* __restrict__ Ah_,
                          const __nv_bfloat16* __restrict__ Al_,
                          const __nv_bfloat16* __restrict__ Bh_,
                          const __nv_bfloat16* __restrict__ Bl_,
                          float* __restrict__ C,
                          const float* __restrict__ bias,
                          char* ds)
{
    constexpr int NC = KDIM / 32;
    int tid = threadIdx.x;
    int lane = tid & 31, wid = tid >> 5;
    int wm = wid & 1, wn = wid >> 1;
    int m0 = by * 128, n0 = bx * 128;
    uint32_t sbase = smem_u32(ds);

    const char* gAh = (const char*)Ah_ + (size_t)m0*KDIM*2;
    const char* gAl = (const char*)Al_ + (size_t)m0*KDIM*2;
    const char* gBh = (const char*)Bh_ + (size_t)n0*FD*2;
    const char* gBl = (const char*)Bl_ + (size_t)n0*FD*2;

    float acc[4][4][4];
    #pragma unroll
    for (int a=0;a<4;a++)
        #pragma unroll
        for (int b=0;b<4;b++)
            #pragma unroll
            for (int r=0;r<4;r++) acc[a][b][r] = 0.f;

    int r0 = tid >> 2, k80 = tid & 3;
    int r1 = r0 + 64;
    uint32_t d0 = tile_off(r0, k80);
    uint32_t d1 = tile_off(r1, k80);

    auto issue = [&](int c){
        size_t koff = (size_t)c*64 + (size_t)k80*16;
        uint32_t sb = sbase + (c % 3)*STGSZ;
        size_t sa0 = (size_t)r0*(KDIM*2) + koff;
        size_t sa1 = (size_t)r1*(KDIM*2) + koff;
        size_t sb0 = (size_t)r0*(FD*2) + koff;
        size_t sb1 = (size_t)r1*(FD*2) + koff;
        cp16(sb + d0,          gAh + sa0);  cp16(sb + d1,          gAh + sa1);
        cp16(sb + TBUF + d0,   gAl + sa0);  cp16(sb + TBUF + d1,   gAl + sa1);
        cp16(sb + 2*TBUF + d0, gBh + sb0);  cp16(sb + 2*TBUF + d1, gBh + sb1);
        cp16(sb + 3*TBUF + d0, gBl + sb0);  cp16(sb + 3*TBUF + d1, gBl + sb1);
        cp_commit();
    };

    issue(0);
    issue(1);

    int a_m  = (lane & 15);
    int a_k8 = (lane >> 4);
    int b_n  = (lane & 7) + ((lane >> 4) << 3);
    int b_k8 = (lane >> 3) & 1;

    for (int c = 0; c < NC; c++){
        if (c + 1 < NC) cp_waitg<1>(); else cp_waitg<0>();
        __syncthreads();
        uint32_t ah = sbase + (c % 3)*STGSZ;
        uint32_t al = ah + TBUF;
        uint32_t bh = ah + 2*TBUF;
        uint32_t bl = ah + 3*TBUF;
        #pragma unroll
        for (int ks = 0; ks < 2; ks++){
            int ks8 = ks*2;
            uint32_t Bhf[2][4], Blf[2][4], Af[4][4];
            #pragma unroll
            for (int p=0; p<2; p++){
                int n = wn*32 + p*16 + b_n;
                uint32_t off = tile_off(n, ks8 + b_k8);
                ldsm4(bh + off, Bhf[p]);
                ldsm4(bl + off, Blf[p]);
            }
            #pragma unroll
            for (int mt=0; mt<4; mt++){
                int m = wm*64 + mt*16 + a_m;
                ldsm4(ah + tile_off(m, ks8 + a_k8), Af[mt]);
            }
            #pragma unroll
            for (int mt=0; mt<4; mt++)
                #pragma unroll
                for (int nt=0; nt<4; nt++)
                    mma16816(acc[mt][nt], Af[mt], &Bhf[nt>>1][(nt&1)*2]);
            #pragma unroll
            for (int mt=0; mt<4; mt++)
                #pragma unroll
                for (int nt=0; nt<4; nt++)
                    mma16816(acc[mt][nt], Af[mt], &Blf[nt>>1][(nt&1)*2]);
            #pragma unroll
            for (int mt=0; mt<4; mt++){
                int m = wm*64 + mt*16 + a_m;
                ldsm4(al + tile_off(m, ks8 + a_k8), Af[mt]);
            }
            #pragma unroll
            for (int mt=0; mt<4; mt++)
                #pragma unroll
                for (int nt=0; nt<4; nt++)
                    mma16816(acc[mt][nt], Af[mt], &Bhf[nt>>1][(nt&1)*2]);
        }
        if (c + 2 < NC) issue(c+2);
    }

    int row = lane >> 2, colb = (lane & 3)*2;
    #pragma unroll
    for (int mt=0; mt<4; mt++){
        #pragma unroll
        for (int h2=0; h2<2; h2++){
            int gm = m0 + wm*64 + mt*16 + row + h2*8;
            if (gm < MDIM){
                #pragma unroll
                for (int nt=0; nt<4; nt++){
                    int cl = wn*32 + nt*8 + colb;
                    int gn = n0 + cl;
                    float v0 = acc[mt][nt][h2*2+0];
                    float v1 = acc[mt][nt][h2*2+1];
                    if (RELU){
                        v0 = fmaxf(v0 + bias[gn], 0.f);
                        v1 = fmaxf(v1 + bias[gn+1], 0.f);
                    }
                    C[(size_t)gm*DD + gn]   = v0;
                    C[(size_t)gm*DD + gn+1] = v1;
                }
            }
        }
    }
}

// ================= big GEMM device core (fused epilogue) =================
#define NCCH  48
__device__ void dev_big(int bx, int by,
                        const float* __restrict__ q_mask,
                        const float* __restrict__ proj_b,
                        char* ds)
{
    __shared__ float s_pwr[5*128];
    __shared__ float s_P[640];
    __shared__ float s_qm[128];
    __shared__ float s_bias[128];
    __shared__ float s_rmax[2][128];
    __shared__ float s_rsum[2][128];

    int tid = threadIdx.x;
    int lane = tid & 31, wid = tid >> 5;
    int wm = wid & 1;
    int wn = wid >> 1;
    int bq  = by;
    int n0  = bx * 128;
    int qi  = bq / 5;
    int pi  = (bq / 100)*5 + (bq % 5);

    uint32_t sbase = smem_u32(ds);

    for (int i = tid; i < 5*128; i += 256){
        int s = i >> 7, c = i & 127;
        s_pwr[i] = g_pw2[((size_t)pi*5 + s)*DD + n0 + c];
    }
    for (int i = tid; i < 640; i += 256) s_P[i] = g_P[(size_t)bq*640 + i];
    if (tid < 128){ s_qm[tid] = q_mask[qi*128 + tid]; s_bias[tid] = proj_b[n0 + tid]; }

    const char* gAh = (const char*)g_Ahi + (size_t)bq*128*3072;
    const char* gAl = (const char*)g_Alo + (size_t)bq*128*3072;
    const char* gBh = (const char*)g_Wh + (size_t)n0*6144 + 3072;
    const char* gBl = (const char*)g_Wl + (size_t)n0*6144 + 3072;

    float acc[4][4][4];
    #pragma unroll
    for (int a=0;a<4;a++)
        #pragma unroll
        for (int b=0;b<4;b++)
            #pragma unroll
            for (int r=0;r<4;r++) acc[a][b][r] = 0.f;

    int r0 = tid >> 2, k80 = tid & 3;
    int r1 = r0 + 64;
    uint32_t d0 = tile_off(r0, k80);
    uint32_t d1 = tile_off(r1, k80);

    auto issue = [&](int c){
        size_t koff = (size_t)c*64 + (size_t)k80*16;
        uint32_t sb = sbase + (c % 3)*STGSZ;
        size_t sa0 = (size_t)r0*3072 + koff;
        size_t sa1 = (size_t)r1*3072 + koff;
        size_t sb0 = (size_t)r0*6144 + koff;
        size_t sb1 = (size_t)r1*6144 + koff;
        cp16(sb + d0,          gAh + sa0);  cp16(sb + d1,          gAh + sa1);
        cp16(sb + TBUF + d0,   gAl + sa0);  cp16(sb + TBUF + d1,   gAl + sa1);
        cp16(sb + 2*TBUF + d0, gBh + sb0);  cp16(sb + 2*TBUF + d1, gBh + sb1);
        cp16(sb + 3*TBUF + d0, gBl + sb0);  cp16(sb + 3*TBUF + d1, gBl + sb1);
        cp_commit();
    };

    issue(0);
    issue(1);

    int a_m  = (lane & 15);
    int a_k8 = (lane >> 4);
    int b_n  = (lane & 7) + ((lane >> 4) << 3);
    int b_k8 = (lane >> 3) & 1;

    for (int c = 0; c < NCCH; c++){
        if (c + 1 < NCCH) cp_waitg<1>(); else cp_waitg<0>();
        __syncthreads();
        uint32_t ah = sbase + (c % 3)*STGSZ;
        uint32_t al = ah + TBUF;
        uint32_t bh = ah + 2*TBUF;
        uint32_t bl = ah + 3*TBUF;
        #pragma unroll
        for (int ks = 0; ks < 2; ks++){
            int ks8 = ks*2;
            uint32_t Bhf[2][4], Blf[2][4], Af[4][4];
            #pragma unroll
            for (int p=0; p<2; p++){
                int n = wn*32 + p*16 + b_n;
                uint32_t off = tile_off(n, ks8 + b_k8);
                ldsm4(bh + off, Bhf[p]);
                ldsm4(bl + off, Blf[p]);
            }
            #pragma unroll
            for (int mt=0; mt<4; mt++){
                int m = wm*64 + mt*16 + a_m;
                ldsm4(ah + tile_off(m, ks8 + a_k8), Af[mt]);
            }
            #pragma unroll
            for (int mt=0; mt<4; mt++)
                #pragma unroll
                for (int nt=0; nt<4; nt++)
                    mma16816(acc[mt][nt], Af[mt], &Bhf[nt>>1][(nt&1)*2]);
            #pragma unroll
            for (int mt=0; mt<4; mt++)
                #pragma unroll
                for (int nt=0; nt<4; nt++)
                    mma16816(acc[mt][nt], Af[mt], &Blf[nt>>1][(nt&1)*2]);
            #pragma unroll
            for (int mt=0; mt<4; mt++){
                int m = wm*64 + mt*16 + a_m;
                ldsm4(al + tile_off(m, ks8 + a_k8), Af[mt]);
            }
            #pragma unroll
            for (int mt=0; mt<4; mt++)
                #pragma unroll
                for (int nt=0; nt<4; nt++)
                    mma16816(acc[mt][nt], Af[mt], &Bhf[nt>>1][(nt&1)*2]);
        }
        if (c + 2 < NCCH) issue(c+2);
    }

    // fused epilogue: +T1 +t2 +bias, relu, max/sum over q via shuffles
    int row = lane >> 2, colb = (lane & 3)*2;
    float lmax[4][2], lsum[4][2];
    #pragma unroll
    for (int nt=0; nt<4; nt++)
        #pragma unroll
        for (int j=0;j<2;j++){ lmax[nt][j] = 0.f; lsum[nt][j] = 0.f; }

    #pragma unroll
    for (int mt=0; mt<4; mt++){
        #pragma unroll
        for (int h2=0; h2<2; h2++){
            int q = wm*64 + mt*16 + row + h2*8;
            float qm = s_qm[q];
            float p0=s_P[q*5+0], p1=s_P[q*5+1], p2=s_P[q*5+2], p3=s_P[q*5+3], p4=s_P[q*5+4];
            const float* t1row = g_T1 + ((size_t)qi*128 + q)*DD + n0;
            #pragma unroll
            for (int nt=0; nt<4; nt++){
                int cl = wn*32 + nt*8 + colb;
                float2 t1 = *(const float2*)(t1row + cl);
                float t2a = qm*(p0*s_pwr[cl] + p1*s_pwr[128+cl] + p2*s_pwr[256+cl]
                              + p3*s_pwr[384+cl] + p4*s_pwr[512+cl]);
                float t2b = qm*(p0*s_pwr[cl+1] + p1*s_pwr[128+cl+1] + p2*s_pwr[256+cl+1]
                              + p3*s_pwr[384+cl+1] + p4*s_pwr[512+cl+1]);
                float v0 = fmaxf(acc[mt][nt][h2*2+0] + t1.x + t2a + s_bias[cl], 0.f);
                float v1 = fmaxf(acc[mt][nt][h2*2+1] + t1.y + t2b + s_bias[cl+1], 0.f);
                lmax[nt][0] = fmaxf(lmax[nt][0], v0); lsum[nt][0] += v0;
                lmax[nt][1] = fmaxf(lmax[nt][1], v1); lsum[nt][1] += v1;
            }
        }
    }
    #pragma unroll
    for (int o = 4; o <= 16; o <<= 1){
        #pragma unroll
        for (int nt=0; nt<4; nt++)
            #pragma unroll
            for (int j=0;j<2;j++){
                lmax[nt][j] = fmaxf(lmax[nt][j], __shfl_xor_sync(0xffffffffu, lmax[nt][j], o));
                lsum[nt][j] += __shfl_xor_sync(0xffffffffu, lsum[nt][j], o);
            }
    }
    if (row == 0){
        #pragma unroll
        for (int nt=0; nt<4; nt++){
            int cl = wn*32 + nt*8 + colb;
            s_rmax[wm][cl]   = lmax[nt][0];  s_rsum[wm][cl]   = lsum[nt][0];
            s_rmax[wm][cl+1] = lmax[nt][1];  s_rsum[wm][cl+1] = lsum[nt][1];
        }
    }
    __syncthreads();
    if (tid < 128){
        g_eqmax[(size_t)bq*DD + n0 + tid] = fmaxf(s_rmax[0][tid], s_rmax[1][tid]);
        g_eqsum[(size_t)bq*DD + n0 + tid] = s_rsum[0][tid] + s_rsum[1][tid];
    }
}

// ================= device paths for fused prep/mid kernels =================
__device__ void dev_proto(int bnk, const float* __restrict__ s_emb,
                          const float* __restrict__ s_mask,
                          const float* __restrict__ s_label)
{
    __shared__ int   tags[128];
    __shared__ float wts[128];
    __shared__ float cnt[TAGS];
    int tid = threadIdx.x;
    if (tid < 128) {
        const float* lr = s_label + ((size_t)bnk*128 + tid)*TAGS;
        float best = lr[0]; int bi = 0;
        #pragma unroll
        for (int s=1;s<TAGS;s++){ float v = lr[s]; if (v > best){ best = v; bi = s; } }
        tags[tid] = bi;
        wts[tid]  = (bi == 0) ? s_mask[bnk*128 + tid] : 1.0f;
    }
    __syncthreads();
    if (tid < TAGS) {
        float c = 0.f;
        for (int t=0;t<128;t++) if (tags[t] == tid) c += wts[t];
        cnt[tid] = c;
    }
    __syncthreads();
    float acc[TAGS][3];
    #pragma unroll
    for (int k=0;k<TAGS;k++)
        #pragma unroll
        for (int j=0;j<3;j++) acc[k][j] = 0.f;
    const float* eb = s_emb + (size_t)bnk*128*DD;
    for (int t=0;t<128;t++){
        int tg = tags[t]; float w = wts[t];
        #pragma unroll
        for (int j=0;j<3;j++){
            float e = eb[t*DD + tid + j*256];
            #pragma unroll
            for (int k=0;k<TAGS;k++)
                acc[k][j] += ((tg == k) ? w : 0.0f) * e;
        }
    }
    #pragma unroll
    for (int k=0;k<TAGS;k++){
        float c = cnt[k];
        float inv = (c > 0.f) ? (1.0f / fmaxf(c, 1.0f)) : 0.0f;
        #pragma unroll
        for (int j=0;j<3;j++){
            int d = tid + j*256;
            g_protok[((size_t)bnk*TAGS + k)*DD + d] = (c > 0.f) ? acc[k][j]*inv : 0.0f;
        }
    }
}

__device__ __forceinline__ void dev_split(int i, const float* __restrict__ src,
                                          __nv_bfloat16* __restrict__ h,
                                          __nv_bfloat16* __restrict__ l, int n)
{
    if (i >= n) return;
    float v = src[i];
    __nv_bfloat16 hh = __float2bfloat16(v);
    h[i] = hh;
    l[i] = __float2bfloat16(v - __bfloat162float(hh));
}

// fused: proto + the three splits
__global__ void __launch_bounds__(256) k_prep(const float* __restrict__ s_emb,
                                              const float* __restrict__ s_mask,
                                              const float* __restrict__ s_label,
                                              const float* __restrict__ proj_w,
                                              const float* __restrict__ rel_w1,
                                              const float* __restrict__ q_emb)
{
    int b = blockIdx.x;
    if (b < 50){ dev_proto(b, s_emb, s_mask, s_label); return; }
    int tid = threadIdx.x;
    if (b < 50 + 9216){ dev_split((b-50)*256 + tid, proj_w, g_Wh, g_Wl, DD*FD); return; }
    if (b < 50 + 2*9216){ dev_split((b-50-9216)*256 + tid, rel_w1, g_RWh, g_RWl, DD*FD); return; }
    dev_split((b-50-2*9216)*256 + tid, q_emb, g_Qh, g_Ql, BNQ*LQ*DD);
}

__global__ void proto_avg_kernel()
{
    int i = blockIdx.x*256 + threadIdx.x;
    int pi = i / (TAGS*DD), rem = i % (TAGS*DD);
    float s = 0.f;
    #pragma unroll
    for (int k=0;k<5;k++) s += g_protok[((size_t)(pi*5 + k))*(TAGS*DD) + rem];
    g_proto[i] = s * 0.2f;
}

// att (with fused s-softmax -> g_P) | pw2
__global__ void __launch_bounds__(256) k_att_pw2(const float* __restrict__ q_emb,
                                                 const float* __restrict__ q_mask,
                                                 const float* __restrict__ Bw)
{
    if (blockIdx.x < BNQ){
        extern __shared__ __align__(128) char dsm[];
        float* sp = (float*)dsm;            // 25 x 768
        int qi = blockIdx.x, tid = threadIdx.x;
        int b = qi / 20;
        const float* pb = g_proto + (size_t)b*25*DD;
        for (int i = tid; i < 25*DD; i += 256) sp[i] = pb[i];
        __syncthreads();
        int wid = tid >> 5, lane = tid & 31;
        const float4* sp4 = (const float4*)sp;
        for (int r = wid; r < 128; r += 8){
            const float4* qr4 = (const float4*)(q_emb + ((size_t)qi*128 + r)*DD);
            float acc[25];
            #pragma unroll
            for (int t=0;t<25;t++) acc[t] = 0.f;
            for (int d4 = lane; d4 < 192; d4 += 32){
                float4 qv = qr4[d4];
                #pragma unroll
                for (int t=0;t<25;t++){
                    float4 sv = sp4[t*192 + d4];
                    acc[t] += qv.x*sv.x + qv.y*sv.y + qv.z*sv.z + qv.w*sv.w;
                }
            }
            float sums[25];
            #pragma unroll
            for (int t=0;t<25;t++) sums[t] = warpSum(acc[t]);
            float qmb = q_mask[qi*128 + r]*100.0f;
            // per-class softmax over s (bias is constant in s -> cancels)
            float P[25];
            #pragma unroll
            for (int c=0;c<5;c++){
                float mx = sums[c*5];
                #pragma unroll
                for (int s=1;s<5;s++) mx = fmaxf(mx, sums[c*5+s]);
                float den = 0.f;
                #pragma unroll
                for (int s=0;s<5;s++){ P[c*5+s] = expf(sums[c*5+s]-mx); den += P[c*5+s]; }
                float inv = 1.0f/den;
                #pragma unroll
                for (int s=0;s<5;s++) P[c*5+s] *= inv;
            }
            if (lane < 25){
                int c = lane / 5, s = lane % 5;
                g_att[(size_t)(qi*5 + c)*640 + s*128 + r] = sums[lane] + qmb;
                g_P  [(size_t)(qi*5 + c)*640 + r*5 + s]   = P[lane];
            }
        }
        return;
    }
    // pw2 path: proto @ W2^T (M=50, N=768, K=768)
    __shared__ float As[16][52];
    __shared__ float Bs[16][68];
    int tid = threadIdx.x;
    int tx = tid & 15, ty = tid >> 4;
    int n0 = (blockIdx.x - BNQ) * 64;
    float acc[4][4];
    #pragma unroll
    for (int i=0;i<4;i++)
        #pragma unroll
        for (int j=0;j<4;j++) acc[i][j] = 0.f;
    int lm = tid >> 2, lk4 = (tid & 3)*4;
    for (int kt = 0; kt < 48; kt++){
        int kg = kt*16 + lk4;
        float4 a0 = (lm < 50) ? *(const float4*)(g_proto + (size_t)lm*DD + kg) : make_float4(0,0,0,0);
        float4 b0 = *(const float4*)(Bw + (size_t)(n0 + lm)*FD + kg);
        __syncthreads();
        if (lm < 50){
            As[lk4+0][lm]=a0.x; As[lk4+1][lm]=a0.y; As[lk4+2][lm]=a0.z; As[lk4+3][lm]=a0.w;
        }
        Bs[lk4+0][lm]=b0.x; Bs[lk4+1][lm]=b0.y; Bs[lk4+2][lm]=b0.z; Bs[lk4+3][lm]=b0.w;
        __syncthreads();
        if (ty < 13){
            #pragma unroll
            for (int kk=0;kk<16;kk++){
                float a[4], b[4];
                #pragma unroll
                for (int i=0;i<4;i++) a[i] = (ty*4+i < 50) ? As[kk][ty*4+i] : 0.f;
                float4 bv = *(const float4*)&Bs[kk][tx*4];
                b[0]=bv.x; b[1]=bv.y; b[2]=bv.z; b[3]=bv.w;
                #pragma unroll
                for (int i=0;i<4;i++)
                    #pragma unroll
                    for (int j=0;j<4;j++) acc[i][j] += a[i]*b[j];
            }
        }
    }
    #pragma unroll
    for (int i=0;i<4;i++){
        int gm = ty*4 + i;
        if (gm < 50){
            #pragma unroll
            for (int j=0;j<4;j++)
                g_pw2[(size_t)gm*DD + n0 + tx*4 + j] = acc[i][j];
        }
    }
}

// ---- supp path (dynamic smem) ----
__device__ void dev_supp(int bq, const float* __restrict__ q_emb, char* dsm)
{
    float* arow = (float*)dsm;          // [5][128]
    float* ps   = arow + 640;           // [5][768]
    float* sc   = ps + 5*DD;            // [8]
    int tid = threadIdx.x;
    int qi = bq / 5;
    int pi = (bq / 100)*5 + (bq % 5);
    for (int i=tid;i<TAGS*128;i+=256) arow[i] = g_att[(size_t)bq*640 + i];
    for (int i=tid;i<TAGS*DD;i+=256) ps[i] = g_proto[(size_t)pi*TAGS*DD + i];
    __syncthreads();
    for (int s=0;s<TAGS;s++){
        float v = (tid<128) ? arow[s*128+tid] : -3.4e38f;
        float wm = warpMax(v);
        if ((tid&31)==0) sc[tid>>5] = wm;
        __syncthreads();
        float bm = sc[0];
        #pragma unroll
        for (int r=1;r<8;r++) bm = fmaxf(bm, sc[r]);
        float e = (tid<128) ? expf(v-bm) : 0.f;
        float wsm = warpSum(e);
        __syncthreads();
        if ((tid&31)==0) sc[tid>>5] = wsm;
        __syncthreads();
        float bs = sc[0];
        #pragma unroll
        for (int r=1;r<8;r++) bs += sc[r];
        if (tid<128) arow[s*128+tid] = e / bs;
        __syncthreads();
    }
    float acc[TAGS][3];
    #pragma unroll
    for (int s=0;s<TAGS;s++)
        #pragma unroll
        for (int j=0;j<3;j++) acc[s][j] = 0.f;
    const float* qb = q_emb + (size_t)qi*128*DD;
    for (int q=0;q<128;q++){
        float w0=arow[q], w1=arow[128+q], w2=arow[256+q], w3=arow[384+q], w4=arow[512+q];
        #pragma unroll
        for (int j=0;j<3;j++){
            float e = qb[q*DD + tid + j*256];
            acc[0][j]+=w0*e; acc[1][j]+=w1*e; acc[2][j]+=w2*e; acc[3][j]+=w3*e; acc[4][j]+=w4*e;
        }
    }
    #pragma unroll
    for (int j=0;j<3;j++){
        int d = tid + j*256;
        #pragma unroll
        for (int s=0;s<TAGS;s++){
            float m1 = ps[s*DD+d];
            float m2 = acc[s][j];
            float f[4] = { m1, m2, fabsf(m1-m2), m1*m2 };
            size_t base = ((size_t)(bq*TAGS + s))*FD;
            #pragma unroll
            for (int cchunk=0;cchunk<4;cchunk++){
                float v = f[cchunk];
                __nv_bfloat16 hh = __float2bfloat16(v);
                g_FSh[base + cchunk*DD + d] = hh;
                g_FSl[base + cchunk*DD + d] = __float2bfloat16(v - __bfloat162float(hh));
            }
        }
    }
}

// ---- aprime path (dynamic smem) ----
__device__ void dev_aprime(int bq, int q0, const float* __restrict__ q_emb,
                           const float* __restrict__ q_mask, char* dsm)
{
    float* ps  = (float*)dsm;      // [5][768]
    float* sP  = ps + 5*DD;        // [640]
    float* sqm = sP + 640;         // [128]
    int tid = threadIdx.x;
    int qi = bq / 5;
    int pi = (bq / 100)*5 + (bq % 5);
    for (int i=tid;i<TAGS*DD;i+=256) ps[i] = g_proto[(size_t)pi*TAGS*DD + i];
    for (int i=tid;i<640;i+=256) sP[i] = g_P[(size_t)bq*640 + i];
    if (tid < 128) sqm[tid] = q_mask[qi*128 + tid];
    __syncthreads();
    for (int q = q0; q < q0 + 32; q++){
        float p0=sP[q*5+0], p1=sP[q*5+1], p2=sP[q*5+2], p3=sP[q*5+3], p4=sP[q*5+4];
        float qm = sqm[q];
        const float* qr = q_emb + ((size_t)qi*128 + q)*DD;
        size_t base = ((size_t)bq*128 + q)*1536;
        for (int d = tid; d < DD; d += 256){
            float m2 = qm * (p0*ps[d] + p1*ps[DD+d] + p2*ps[2*DD+d] + p3*ps[3*DD+d] + p4*ps[4*DD+d]);
            float m1 = qr[d];
            float va = fabsf(m1 - m2);
            float vp = m1*m2;
            __nv_bfloat16 ah = __float2bfloat16(va);
            __nv_bfloat16 al = __float2bfloat16(va - __bfloat162float(ah));
            __nv_bfloat16 ph = __float2bfloat16(vp);
            __nv_bfloat16 pl = __float2bfloat16(vp - __bfloat162float(ph));
            g_Ahi[base + d]      = ah;  g_Alo[base + d]      = al;
            g_Ahi[base + DD + d] = ph;  g_Alo[base + DD + d] = pl;
        }
    }
}

// fused mid: supp(200) | T1 hgemm(240) | aprime(800)
__global__ void __launch_bounds__(256,2) k_mid(const float* __restrict__ q_emb,
                                               const float* __restrict__ q_mask)
{
    extern __shared__ __align__(128) char ds[];
    int b = blockIdx.x;
    if (b < 200){ dev_supp(b, q_emb, ds); return; }
    if (b < 440){
        int i = b - 200;
        dev_hgemm<768,5120,false>(i % 6, i / 6, g_Qh, g_Ql, g_Wh, g_Wl, g_T1, nullptr, ds);
        return;
    }
    int i = b - 440;
    dev_aprime(i % 200, (i / 200)*32, q_emb, q_mask, ds);
}

// fused big: big_mma(1200) | es hgemm(48)
__global__ void __launch_bounds__(256,2) k_big(const float* __restrict__ q_mask,
                                               const float* __restrict__ proj_b)
{
    extern __shared__ __align__(128) char ds[];
    int b = blockIdx.x;
    if (b < 1200){ dev_big(b % 6, b / 6, q_mask, proj_b, ds); return; }
    int i = b - 1200;
    dev_hgemm<3072,1000,true>(i % 6, i / 6, g_FSh, g_FSl, g_Wh, g_Wl, g_es, proj_b, ds);
}

// ---------------- cat assembly -> bf16 hi/lo ----------------
__global__ void cat_kernel(const float* __restrict__ q_mask)
{
    int bq = blockIdx.x, tid = threadIdx.x;
    int qi = bq / 5;
    __shared__ float sc[8];
    __shared__ float qs_s;
    float v = (tid < 128) ? q_mask[qi*128 + tid] : 0.f;
    float ws = warpSum(v);
    if ((tid&31)==0) sc[tid>>5] = ws;
    __syncthreads();
    if (tid == 0){
        float q = 0.f;
        #pragma unroll
        for (int r=0;r<8;r++) q += sc[r];
        qs_s = q;
    }
    __syncthreads();
    float qs = qs_s;
    #pragma unroll
    for (int j=0;j<3;j++){
        int d = tid + j*256;
        float mx = 0.f, sm = 0.f;
        #pragma unroll
        for (int s=0;s<TAGS;s++){
            float e = g_es[((size_t)(bq*TAGS + s))*DD + d];
            mx = fmaxf(mx, e); sm += e;
        }
        float f[4] = { g_eqmax[(size_t)bq*DD + d],
                       g_eqsum[(size_t)bq*DD + d] / qs,
                       mx, sm * 0.2f };
        size_t b = (size_t)bq*FD;
        #pragma unroll
        for (int cchunk=0;cchunk<4;cchunk++){
            float val = f[cchunk];
            __nv_bfloat16 hh = __float2bfloat16(val);
            g_Ch[b + cchunk*DD + d] = hh;
            g_Cl[b + cchunk*DD + d] = __float2bfloat16(val - __bfloat162float(hh));
        }
    }
}

// ---------------- h = relu(cat @ rel_w1^T + b1) ----------------
__global__ void __launch_bounds__(256,2) k_h(const float* __restrict__ rel_b1)
{
    extern __shared__ __align__(128) char ds[];
    dev_hgemm<3072,200,true>(blockIdx.x, blockIdx.y, g_Ch, g_Cl, g_RWh, g_RWl, g_h, rel_b1, ds);
}

// ---------------- final logits ----------------
__global__ void logits_kernel(const float* __restrict__ rel_w2,
                              const float* __restrict__ rel_b2,
                              float* __restrict__ out)
{
    int g = blockIdx.x*8 + (threadIdx.x >> 5);
    if (g >= BQC) return;
    int lane = threadIdx.x & 31;
    float s = 0.f;
    for (int d=lane; d<DD; d+=32) s += rel_w2[d]*g_h[(size_t)g*DD + d];
    s = warpSum(s);
    if (!lane) out[g] = s + rel_b2[0];
}

// ---------------- launcher ----------------
extern "C" void kernel_launch(void* const* d_in, const int* in_sizes, int n_in,
                              void* d_out, int out_size)
{
    const float* s_emb   = (const float*)d_in[0];
    const float* q_emb   = (const float*)d_in[1];
    const float* s_mask  = (const float*)d_in[2];
    const float* q_mask  = (const float*)d_in[3];
    const float* s_label = (const float*)d_in[4];
    const float* proj_w  = (const float*)d_in[5];
    const float* proj_b  = (const float*)d_in[6];
    const float* rel_w1  = (const float*)d_in[7];
    const float* rel_b1  = (const float*)d_in[8];
    const float* rel_w2  = (const float*)d_in[9];
    const float* rel_b2  = (const float*)d_in[10];
    float* out = (float*)d_out;

    static bool attr_set = false;
    if (!attr_set){
        cudaFuncSetAttribute(k_mid, cudaFuncAttributeMaxDynamicSharedMemorySize, DSMEM);
        cudaFuncSetAttribute(k_big, cudaFuncAttributeMaxDynamicSharedMemorySize, DSMEM);
        cudaFuncSetAttribute(k_h,   cudaFuncAttributeMaxDynamicSharedMemorySize, DSMEM);
        cudaFuncSetAttribute(k_att_pw2, cudaFuncAttributeMaxDynamicSharedMemorySize, 25*DD*4);
        attr_set = true;
    }

    k_prep          <<<50 + 2*9216 + 15360, 256>>>(s_emb, s_mask, s_label, proj_w, rel_w1, q_emb);
    proto_avg_kernel<<<150, 256>>>();
    k_att_pw2       <<<BNQ + 12, 256, 25*DD*4>>>(q_emb, q_mask, proj_w + DD);
    k_mid           <<<1240, 256, DSMEM>>>(q_emb, q_mask);
    k_big           <<<1248, 256, DSMEM>>>(q_mask, proj_b);
    cat_kernel      <<<BQC, 256>>>(q_mask);
    k_h             <<<dim3(6,2), 256, DSMEM>>>(rel_b1);
    logits_kernel   <<<25, 256>>>(rel_w2, rel_b2, out);
}

// round 8
// speedup vs baseline: 2.8344x; 1.0807x over previous
#include <cuda_runtime.h>
#include <cuda_bf16.h>
#include <math.h>
#include <stdint.h>

// Problem constants (fixed by setup_inputs)
#define DD    768
#define TAGS  5
#define LQ    128
#define BQC   200      // B*N*Q*N
#define BNQ   40       // B*N*Q
#define BNKC  50       // B*N*K
#define NPROT 10       // B*N
#define FD    3072     // 4*D
#define MBIG  25600    // BQC*LQ

// ---------------- scratch (device globals) --------------
__device__ float g_protok[BNKC*TAGS*DD];
__device__ float g_proto [NPROT*TAGS*DD];
__device__ float g_pw2   [NPROT*TAGS*DD];
__device__ float g_att   [BQC*TAGS*LQ];
__device__ float g_P     [BQC*LQ*TAGS];
__device__ __nv_bfloat16 g_Ahi[(size_t)MBIG*1536];
__device__ __nv_bfloat16 g_Alo[(size_t)MBIG*1536];
__device__ __nv_bfloat16 g_Wh [(size_t)DD*FD];
__device__ __nv_bfloat16 g_Wl [(size_t)DD*FD];
__device__ __nv_bfloat16 g_RWh[(size_t)DD*FD];
__device__ __nv_bfloat16 g_RWl[(size_t)DD*FD];
__device__ __nv_bfloat16 g_Qh [(size_t)BNQ*LQ*DD];
__device__ __nv_bfloat16 g_Ql [(size_t)BNQ*LQ*DD];
__device__ __nv_bfloat16 g_FSh[(size_t)1024*FD];
__device__ __nv_bfloat16 g_FSl[(size_t)1024*FD];
__device__ __nv_bfloat16 g_Ch [(size_t)256*FD];
__device__ __nv_bfloat16 g_Cl [(size_t)256*FD];
__device__ float g_T1    [BNQ*LQ*DD];
__device__ float g_es    [BQC*TAGS*DD];
__device__ float g_eqmax [BQC*DD];
__device__ float g_eqsum [BQC*DD];
__device__ float g_h     [BQC*DD];

__device__ __forceinline__ float warpMax(float v){
    #pragma unroll
    for (int o=16;o;o>>=1) v = fmaxf(v, __shfl_xor_sync(0xffffffffu, v, o));
    return v;
}
__device__ __forceinline__ float warpSum(float v){
    #pragma unroll
    for (int o=16;o;o>>=1) v += __shfl_xor_sync(0xffffffffu, v, o);
    return v;
}

// ================= HMMA helpers =================
__device__ __forceinline__ uint32_t smem_u32(const void* p) {
    uint32_t a;
    asm("{ .reg .u64 t; cvta.to.shared.u64 t, %1; cvt.u32.u64 %0, t; }" : "=r"(a) : "l"(p));
    return a;
}
__device__ __forceinline__ void cp16(uint32_t dst, const void* src){
    asm volatile("cp.async.cg.shared.global [%0], [%1], 16;" :: "r"(dst), "l"(src) : "memory");
}
__device__ __forceinline__ void cp_commit(){ asm volatile("cp.async.commit_group;" ::: "memory"); }
template<int N> __device__ __forceinline__ void cp_waitg(){
    asm volatile("cp.async.wait_group %0;" :: "n"(N) : "memory");
}
__device__ __forceinline__ void ldsm4(uint32_t a, uint32_t* r){
    asm volatile("ldmatrix.sync.aligned.m8n8.x4.shared.b16 {%0,%1,%2,%3}, [%4];"
        : "=r"(r[0]),"=r"(r[1]),"=r"(r[2]),"=r"(r[3]) : "r"(a));
}
__device__ __forceinline__ void mma16816(float* c, const uint32_t* a, const uint32_t* b){
    asm volatile("mma.sync.aligned.m16n8k16.row.col.f32.bf16.bf16.f32 "
        "{%0,%1,%2,%3},{%4,%5,%6,%7},{%8,%9},{%0,%1,%2,%3};"
        : "+f"(c[0]),"+f"(c[1]),"+f"(c[2]),"+f"(c[3])
        : "r"(a[0]),"r"(a[1]),"r"(a[2]),"r"(a[3]), "r"(b[0]),"r"(b[1]));
}
__device__ __forceinline__ uint32_t tile_off(int m, int k8){
    return (uint32_t)((m*4 + (k8 ^ ((m>>1)&3))) << 4);
}

#define TBUF  8192
#define STGSZ (4*TBUF)
#define DSMEM (3*STGSZ)

// ================= generic HMMA GEMM device core =================
template<int KDIM, int MDIM, bool RELU>
__device__ void dev_hgemm(int bx, int by,
                          const __nv_bfloat16* __restrict__ Ah_,
                          const __nv_bfloat16* __restrict__ Al_,
                          const __nv_bfloat16* __restrict__ Bh_,
                          const __nv_bfloat16* __restrict__ Bl_,
                          float* __restrict__ C,
                          const float* __restrict__ bias,
                          char* ds)
{
    constexpr int NC = KDIM / 32;
    int tid = threadIdx.x;
    int lane = tid & 31, wid = tid >> 5;
    int wm = wid & 1, wn = wid >> 1;
    int m0 = by * 128, n0 = bx * 128;
    uint32_t sbase = smem_u32(ds);

    const char* gAh = (const char*)Ah_ + (size_t)m0*KDIM*2;
    const char* gAl = (const char*)Al_ + (size_t)m0*KDIM*2;
    const char* gBh = (const char*)Bh_ + (size_t)n0*FD*2;
    const char* gBl = (const char*)Bl_ + (size_t)n0*FD*2;

    float acc[4][4][4];
    #pragma unroll
    for (int a=0;a<4;a++)
        #pragma unroll
        for (int b=0;b<4;b++)
            #pragma unroll
            for (int r=0;r<4;r++) acc[a][b][r] = 0.f;

    int r0 = tid >> 2, k80 = tid & 3;
    int r1 = r0 + 64;
    uint32_t d0 = tile_off(r0, k80);
    uint32_t d1 = tile_off(r1, k80);

    auto issue = [&](int c){
        size_t koff = (size_t)c*64 + (size_t)k80*16;
        uint32_t sb = sbase + (c % 3)*STGSZ;
        size_t sa0 = (size_t)r0*(KDIM*2) + koff;
        size_t sa1 = (size_t)r1*(KDIM*2) + koff;
        size_t sb0 = (size_t)r0*(FD*2) + koff;
        size_t sb1 = (size_t)r1*(FD*2) + koff;
        cp16(sb + d0,          gAh + sa0);  cp16(sb + d1,          gAh + sa1);
        cp16(sb + TBUF + d0,   gAl + sa0);  cp16(sb + TBUF + d1,   gAl + sa1);
        cp16(sb + 2*TBUF + d0, gBh + sb0);  cp16(sb + 2*TBUF + d1, gBh + sb1);
        cp16(sb + 3*TBUF + d0, gBl + sb0);  cp16(sb + 3*TBUF + d1, gBl + sb1);
        cp_commit();
    };

    issue(0);
    issue(1);

    int a_m  = (lane & 15);
    int a_k8 = (lane >> 4);
    int b_n  = (lane & 7) + ((lane >> 4) << 3);
    int b_k8 = (lane >> 3) & 1;

    for (int c = 0; c < NC; c++){
        if (c + 1 < NC) cp_waitg<1>(); else cp_waitg<0>();
        __syncthreads();
        uint32_t ah = sbase + (c % 3)*STGSZ;
        uint32_t al = ah + TBUF;
        uint32_t bh = ah + 2*TBUF;
        uint32_t bl = ah + 3*TBUF;
        #pragma unroll
        for (int ks = 0; ks < 2; ks++){
            int ks8 = ks*2;
            uint32_t Bhf[2][4], Blf[2][4], Af[4][4];
            #pragma unroll
            for (int p=0; p<2; p++){
                int n = wn*32 + p*16 + b_n;
                uint32_t off = tile_off(n, ks8 + b_k8);
                ldsm4(bh + off, Bhf[p]);
                ldsm4(bl + off, Blf[p]);
            }
            #pragma unroll
            for (int mt=0; mt<4; mt++){
                int m = wm*64 + mt*16 + a_m;
                ldsm4(ah + tile_off(m, ks8 + a_k8), Af[mt]);
            }
            #pragma unroll
            for (int mt=0; mt<4; mt++)
                #pragma unroll
                for (int nt=0; nt<4; nt++)
                    mma16816(acc[mt][nt], Af[mt], &Bhf[nt>>1][(nt&1)*2]);
            #pragma unroll
            for (int mt=0; mt<4; mt++)
                #pragma unroll
                for (int nt=0; nt<4; nt++)
                    mma16816(acc[mt][nt], Af[mt], &Blf[nt>>1][(nt&1)*2]);
            #pragma unroll
            for (int mt=0; mt<4; mt++){
                int m = wm*64 + mt*16 + a_m;
                ldsm4(al + tile_off(m, ks8 + a_k8), Af[mt]);
            }
            #pragma unroll
            for (int mt=0; mt<4; mt++)
                #pragma unroll
                for (int nt=0; nt<4; nt++)
                    mma16816(acc[mt][nt], Af[mt], &Bhf[nt>>1][(nt&1)*2]);
        }
        if (c + 2 < NC) issue(c+2);
    }

    int row = lane >> 2, colb = (lane & 3)*2;
    #pragma unroll
    for (int mt=0; mt<4; mt++){
        #pragma unroll
        for (int h2=0; h2<2; h2++){
            int gm = m0 + wm*64 + mt*16 + row + h2*8;
            if (gm < MDIM){
                #pragma unroll
                for (int nt=0; nt<4; nt++){
                    int cl = wn*32 + nt*8 + colb;
                    int gn = n0 + cl;
                    float v0 = acc[mt][nt][h2*2+0];
                    float v1 = acc[mt][nt][h2*2+1];
                    if (RELU){
                        v0 = fmaxf(v0 + bias[gn], 0.f);
                        v1 = fmaxf(v1 + bias[gn+1], 0.f);
                    }
                    C[(size_t)gm*DD + gn]   = v0;
                    C[(size_t)gm*DD + gn+1] = v1;
                }
            }
        }
    }
}

// ================= big GEMM device core (fused epilogue) =================
#define NCCH  48
__device__ void dev_big(int bx, int by,
                        const float* __restrict__ q_mask,
                        const float* __restrict__ proj_b,
                        char* ds)
{
    __shared__ float s_pwr[5*128];
    __shared__ float s_P[640];
    __shared__ float s_qm[128];
    __shared__ float s_bias[128];
    __shared__ float s_rmax[2][128];
    __shared__ float s_rsum[2][128];

    int tid = threadIdx.x;
    int lane = tid & 31, wid = tid >> 5;
    int wm = wid & 1;
    int wn = wid >> 1;
    int bq  = by;
    int n0  = bx * 128;
    int qi  = bq / 5;
    int pi  = (bq / 100)*5 + (bq % 5);

    uint32_t sbase = smem_u32(ds);

    for (int i = tid; i < 5*128; i += 256){
        int s = i >> 7, c = i & 127;
        s_pwr[i] = g_pw2[((size_t)pi*5 + s)*DD + n0 + c];
    }
    for (int i = tid; i < 640; i += 256) s_P[i] = g_P[(size_t)bq*640 + i];
    if (tid < 128){ s_qm[tid] = q_mask[qi*128 + tid]; s_bias[tid] = proj_b[n0 + tid]; }

    const char* gAh = (const char*)g_Ahi + (size_t)bq*128*3072;
    const char* gAl = (const char*)g_Alo + (size_t)bq*128*3072;
    const char* gBh = (const char*)g_Wh + (size_t)n0*6144 + 3072;
    const char* gBl = (const char*)g_Wl + (size_t)n0*6144 + 3072;

    float acc[4][4][4];
    #pragma unroll
    for (int a=0;a<4;a++)
        #pragma unroll
        for (int b=0;b<4;b++)
            #pragma unroll
            for (int r=0;r<4;r++) acc[a][b][r] = 0.f;

    int r0 = tid >> 2, k80 = tid & 3;
    int r1 = r0 + 64;
    uint32_t d0 = tile_off(r0, k80);
    uint32_t d1 = tile_off(r1, k80);

    auto issue = [&](int c){
        size_t koff = (size_t)c*64 + (size_t)k80*16;
        uint32_t sb = sbase + (c % 3)*STGSZ;
        size_t sa0 = (size_t)r0*3072 + koff;
        size_t sa1 = (size_t)r1*3072 + koff;
        size_t sb0 = (size_t)r0*6144 + koff;
        size_t sb1 = (size_t)r1*6144 + koff;
        cp16(sb + d0,          gAh + sa0);  cp16(sb + d1,          gAh + sa1);
        cp16(sb + TBUF + d0,   gAl + sa0);  cp16(sb + TBUF + d1,   gAl + sa1);
        cp16(sb + 2*TBUF + d0, gBh + sb0);  cp16(sb + 2*TBUF + d1, gBh + sb1);
        cp16(sb + 3*TBUF + d0, gBl + sb0);  cp16(sb + 3*TBUF + d1, gBl + sb1);
        cp_commit();
    };

    issue(0);
    issue(1);

    int a_m  = (lane & 15);
    int a_k8 = (lane >> 4);
    int b_n  = (lane & 7) + ((lane >> 4) << 3);
    int b_k8 = (lane >> 3) & 1;

    for (int c = 0; c < NCCH; c++){
        if (c + 1 < NCCH) cp_waitg<1>(); else cp_waitg<0>();
        __syncthreads();
        uint32_t ah = sbase + (c % 3)*STGSZ;
        uint32_t al = ah + TBUF;
        uint32_t bh = ah + 2*TBUF;
        uint32_t bl = ah + 3*TBUF;
        #pragma unroll
        for (int ks = 0; ks < 2; ks++){
            int ks8 = ks*2;
            uint32_t Bhf[2][4], Blf[2][4], Af[4][4];
            #pragma unroll
            for (int p=0; p<2; p++){
                int n = wn*32 + p*16 + b_n;
                uint32_t off = tile_off(n, ks8 + b_k8);
                ldsm4(bh + off, Bhf[p]);
                ldsm4(bl + off, Blf[p]);
            }
            #pragma unroll
            for (int mt=0; mt<4; mt++){
                int m = wm*64 + mt*16 + a_m;
                ldsm4(ah + tile_off(m, ks8 + a_k8), Af[mt]);
            }
            #pragma unroll
            for (int mt=0; mt<4; mt++)
                #pragma unroll
                for (int nt=0; nt<4; nt++)
                    mma16816(acc[mt][nt], Af[mt], &Bhf[nt>>1][(nt&1)*2]);
            #pragma unroll
            for (int mt=0; mt<4; mt++)
                #pragma unroll
                for (int nt=0; nt<4; nt++)
                    mma16816(acc[mt][nt], Af[mt], &Blf[nt>>1][(nt&1)*2]);
            #pragma unroll
            for (int mt=0; mt<4; mt++){
                int m = wm*64 + mt*16 + a_m;
                ldsm4(al + tile_off(m, ks8 + a_k8), Af[mt]);
            }
            #pragma unroll
            for (int mt=0; mt<4; mt++)
                #pragma unroll
                for (int nt=0; nt<4; nt++)
                    mma16816(acc[mt][nt], Af[mt], &Bhf[nt>>1][(nt&1)*2]);
        }
        if (c + 2 < NCCH) issue(c+2);
    }

    // fused epilogue
    int row = lane >> 2, colb = (lane & 3)*2;
    float lmax[4][2], lsum[4][2];
    #pragma unroll
    for (int nt=0; nt<4; nt++)
        #pragma unroll
        for (int j=0;j<2;j++){ lmax[nt][j] = 0.f; lsum[nt][j] = 0.f; }

    #pragma unroll
    for (int mt=0; mt<4; mt++){
        #pragma unroll
        for (int h2=0; h2<2; h2++){
            int q = wm*64 + mt*16 + row + h2*8;
            float qm = s_qm[q];
            float p0=s_P[q*5+0], p1=s_P[q*5+1], p2=s_P[q*5+2], p3=s_P[q*5+3], p4=s_P[q*5+4];
            const float* t1row = g_T1 + ((size_t)qi*128 + q)*DD + n0;
            #pragma unroll
            for (int nt=0; nt<4; nt++){
                int cl = wn*32 + nt*8 + colb;
                float2 t1 = *(const float2*)(t1row + cl);
                float t2a = qm*(p0*s_pwr[cl] + p1*s_pwr[128+cl] + p2*s_pwr[256+cl]
                              + p3*s_pwr[384+cl] + p4*s_pwr[512+cl]);
                float t2b = qm*(p0*s_pwr[cl+1] + p1*s_pwr[128+cl+1] + p2*s_pwr[256+cl+1]
                              + p3*s_pwr[384+cl+1] + p4*s_pwr[512+cl+1]);
                float v0 = fmaxf(acc[mt][nt][h2*2+0] + t1.x + t2a + s_bias[cl], 0.f);
                float v1 = fmaxf(acc[mt][nt][h2*2+1] + t1.y + t2b + s_bias[cl+1], 0.f);
                lmax[nt][0] = fmaxf(lmax[nt][0], v0); lsum[nt][0] += v0;
                lmax[nt][1] = fmaxf(lmax[nt][1], v1); lsum[nt][1] += v1;
            }
        }
    }
    #pragma unroll
    for (int o = 4; o <= 16; o <<= 1){
        #pragma unroll
        for (int nt=0; nt<4; nt++)
            #pragma unroll
            for (int j=0;j<2;j++){
                lmax[nt][j] = fmaxf(lmax[nt][j], __shfl_xor_sync(0xffffffffu, lmax[nt][j], o));
                lsum[nt][j] += __shfl_xor_sync(0xffffffffu, lsum[nt][j], o);
            }
    }
    if (row == 0){
        #pragma unroll
        for (int nt=0; nt<4; nt++){
            int cl = wn*32 + nt*8 + colb;
            s_rmax[wm][cl]   = lmax[nt][0];  s_rsum[wm][cl]   = lsum[nt][0];
            s_rmax[wm][cl+1] = lmax[nt][1];  s_rsum[wm][cl+1] = lsum[nt][1];
        }
    }
    __syncthreads();
    if (tid < 128){
        g_eqmax[(size_t)bq*DD + n0 + tid] = fmaxf(s_rmax[0][tid], s_rmax[1][tid]);
        g_eqsum[(size_t)bq*DD + n0 + tid] = s_rsum[0][tid] + s_rsum[1][tid];
    }
}

// ================= prep paths =================
__device__ void dev_proto(int bnk, const float* __restrict__ s_emb,
                          const float* __restrict__ s_mask,
                          const float* __restrict__ s_label)
{
    __shared__ int   tags[128];
    __shared__ float wts[128];
    __shared__ float cnt[TAGS];
    int tid = threadIdx.x;
    if (tid < 128) {
        const float* lr = s_label + ((size_t)bnk*128 + tid)*TAGS;
        float best = lr[0]; int bi = 0;
        #pragma unroll
        for (int s=1;s<TAGS;s++){ float v = lr[s]; if (v > best){ best = v; bi = s; } }
        tags[tid] = bi;
        wts[tid]  = (bi == 0) ? s_mask[bnk*128 + tid] : 1.0f;
    }
    __syncthreads();
    if (tid < TAGS) {
        float c = 0.f;
        for (int t=0;t<128;t++) if (tags[t] == tid) c += wts[t];
        cnt[tid] = c;
    }
    __syncthreads();
    float acc[TAGS][3];
    #pragma unroll
    for (int k=0;k<TAGS;k++)
        #pragma unroll
        for (int j=0;j<3;j++) acc[k][j] = 0.f;
    const float* eb = s_emb + (size_t)bnk*128*DD;
    for (int t=0;t<128;t++){
        int tg = tags[t]; float w = wts[t];
        #pragma unroll
        for (int j=0;j<3;j++){
            float e = eb[t*DD + tid + j*256];
            #pragma unroll
            for (int k=0;k<TAGS;k++)
                acc[k][j] += ((tg == k) ? w : 0.0f) * e;
        }
    }
    #pragma unroll
    for (int k=0;k<TAGS;k++){
        float c = cnt[k];
        float inv = (c > 0.f) ? (1.0f / fmaxf(c, 1.0f)) : 0.0f;
        #pragma unroll
        for (int j=0;j<3;j++){
            int d = tid + j*256;
            g_protok[((size_t)bnk*TAGS + k)*DD + d] = (c > 0.f) ? acc[k][j]*inv : 0.0f;
        }
    }
}

__device__ __forceinline__ void dev_split(int i, const float* __restrict__ src,
                                          __nv_bfloat16* __restrict__ h,
                                          __nv_bfloat16* __restrict__ l, int n)
{
    if (i >= n) return;
    float v = src[i];
    __nv_bfloat16 hh = __float2bfloat16(v);
    h[i] = hh;
    l[i] = __float2bfloat16(v - __bfloat162float(hh));
}

__global__ void __launch_bounds__(256) k_prep(const float* __restrict__ s_emb,
                                              const float* __restrict__ s_mask,
                                              const float* __restrict__ s_label,
                                              const float* __restrict__ proj_w,
                                              const float* __restrict__ rel_w1,
                                              const float* __restrict__ q_emb)
{
    int b = blockIdx.x;
    if (b < 50){ dev_proto(b, s_emb, s_mask, s_label); return; }
    int tid = threadIdx.x;
    if (b < 50 + 9216){ dev_split((b-50)*256 + tid, proj_w, g_Wh, g_Wl, DD*FD); return; }
    if (b < 50 + 2*9216){ dev_split((b-50-9216)*256 + tid, rel_w1, g_RWh, g_RWl, DD*FD); return; }
    dev_split((b-50-2*9216)*256 + tid, q_emb, g_Qh, g_Ql, BNQ*LQ*DD);
}

__global__ void proto_avg_kernel()
{
    int i = blockIdx.x*256 + threadIdx.x;
    int pi = i / (TAGS*DD), rem = i % (TAGS*DD);
    float s = 0.f;
    #pragma unroll
    for (int k=0;k<5;k++) s += g_protok[((size_t)(pi*5 + k))*(TAGS*DD) + rem];
    g_proto[i] = s * 0.2f;
}

// ================= att (fused s-softmax) | pw2 | T1 hgemm =================
__global__ void __launch_bounds__(256,2) k_att_pw2_t1(const float* __restrict__ q_emb,
                                                      const float* __restrict__ q_mask,
                                                      const float* __restrict__ Bw)
{
    extern __shared__ __align__(128) char ds[];
    if (blockIdx.x < BNQ){
        float* sp = (float*)ds;            // 25 x 768
        int qi = blockIdx.x, tid = threadIdx.x;
        int b = qi / 20;
        const float* pb = g_proto + (size_t)b*25*DD;
        for (int i = tid; i < 25*DD; i += 256) sp[i] = pb[i];
        __syncthreads();
        int wid = tid >> 5, lane = tid & 31;
        const float4* sp4 = (const float4*)sp;
        for (int r = wid; r < 128; r += 8){
            const float4* qr4 = (const float4*)(q_emb + ((size_t)qi*128 + r)*DD);
            float acc[25];
            #pragma unroll
            for (int t=0;t<25;t++) acc[t] = 0.f;
            for (int d4 = lane; d4 < 192; d4 += 32){
                float4 qv = qr4[d4];
                #pragma unroll
                for (int t=0;t<25;t++){
                    float4 sv = sp4[t*192 + d4];
                    acc[t] += qv.x*sv.x + qv.y*sv.y + qv.z*sv.z + qv.w*sv.w;
                }
            }
            float sums[25];
            #pragma unroll
            for (int t=0;t<25;t++) sums[t] = warpSum(acc[t]);
            float qmb = q_mask[qi*128 + r]*100.0f;
            float P[25];
            #pragma unroll
            for (int c=0;c<5;c++){
                float mx = sums[c*5];
                #pragma unroll
                for (int s=1;s<5;s++) mx = fmaxf(mx, sums[c*5+s]);
                float den = 0.f;
                #pragma unroll
                for (int s=0;s<5;s++){ P[c*5+s] = expf(sums[c*5+s]-mx); den += P[c*5+s]; }
                float inv = 1.0f/den;
                #pragma unroll
                for (int s=0;s<5;s++) P[c*5+s] *= inv;
            }
            if (lane < 25){
                int c = lane / 5, s = lane % 5;
                g_att[(size_t)(qi*5 + c)*640 + s*128 + r] = sums[lane] + qmb;
                g_P  [(size_t)(qi*5 + c)*640 + r*5 + s]   = P[lane];
            }
        }
        return;
    }
    if (blockIdx.x < BNQ + 12){
        // pw2 path: proto @ W2^T (M=50, N=768, K=768)
        __shared__ float As[16][52];
        __shared__ float Bs[16][68];
        int tid = threadIdx.x;
        int tx = tid & 15, ty = tid >> 4;
        int n0 = (blockIdx.x - BNQ) * 64;
        float acc[4][4];
        #pragma unroll
        for (int i=0;i<4;i++)
            #pragma unroll
            for (int j=0;j<4;j++) acc[i][j] = 0.f;
        int lm = tid >> 2, lk4 = (tid & 3)*4;
        for (int kt = 0; kt < 48; kt++){
            int kg = kt*16 + lk4;
            float4 a0 = (lm < 50) ? *(const float4*)(g_proto + (size_t)lm*DD + kg) : make_float4(0,0,0,0);
            float4 b0 = *(const float4*)(Bw + (size_t)(n0 + lm)*FD + kg);
            __syncthreads();
            if (lm < 50){
                As[lk4+0][lm]=a0.x; As[lk4+1][lm]=a0.y; As[lk4+2][lm]=a0.z; As[lk4+3][lm]=a0.w;
            }
            Bs[lk4+0][lm]=b0.x; Bs[lk4+1][lm]=b0.y; Bs[lk4+2][lm]=b0.z; Bs[lk4+3][lm]=b0.w;
            __syncthreads();
            if (ty < 13){
                #pragma unroll
                for (int kk=0;kk<16;kk++){
                    float a[4], b[4];
                    #pragma unroll
                    for (int i=0;i<4;i++) a[i] = (ty*4+i < 50) ? As[kk][ty*4+i] : 0.f;
                    float4 bv = *(const float4*)&Bs[kk][tx*4];
                    b[0]=bv.x; b[1]=bv.y; b[2]=bv.z; b[3]=bv.w;
                    #pragma unroll
                    for (int i=0;i<4;i++)
                        #pragma unroll
                        for (int j=0;j<4;j++) acc[i][j] += a[i]*b[j];
                }
            }
        }
        #pragma unroll
        for (int i=0;i<4;i++){
            int gm = ty*4 + i;
            if (gm < 50){
                #pragma unroll
                for (int j=0;j<4;j++)
                    g_pw2[(size_t)gm*DD + n0 + tx*4 + j] = acc[i][j];
            }
        }
        return;
    }
    // T1 hgemm path (240 CTAs)
    int i = blockIdx.x - (BNQ + 12);
    dev_hgemm<768,5120,false>(i % 6, i / 6, g_Qh, g_Ql, g_Wh, g_Wl, g_T1, nullptr, ds);
}

// ================= light kernel: supp(200) + aprime(800) =================
__global__ void __launch_bounds__(256,4) k_light(const float* __restrict__ q_emb,
                                                 const float* __restrict__ q_mask)
{
    __shared__ float sbuf[4616];
    int b = blockIdx.x;
    int tid = threadIdx.x;
    if (b < 200){
        // supp
        int bq = b;
        float* arow = sbuf;            // 640
        float* ps   = sbuf + 640;      // 3840
        float* sc   = sbuf + 4480;     // 8
        int qi = bq / 5;
        int pi = (bq / 100)*5 + (bq % 5);
        for (int i=tid;i<TAGS*128;i+=256) arow[i] = g_att[(size_t)bq*640 + i];
        for (int i=tid;i<TAGS*DD;i+=256) ps[i] = g_proto[(size_t)pi*TAGS*DD + i];
        __syncthreads();
        for (int s=0;s<TAGS;s++){
            float v = (tid<128) ? arow[s*128+tid] : -3.4e38f;
            float wm = warpMax(v);
            if ((tid&31)==0) sc[tid>>5] = wm;
            __syncthreads();
            float bm = sc[0];
            #pragma unroll
            for (int r=1;r<8;r++) bm = fmaxf(bm, sc[r]);
            float e = (tid<128) ? expf(v-bm) : 0.f;
            float wsm = warpSum(e);
            __syncthreads();
            if ((tid&31)==0) sc[tid>>5] = wsm;
            __syncthreads();
            float bs = sc[0];
            #pragma unroll
            for (int r=1;r<8;r++) bs += sc[r];
            if (tid<128) arow[s*128+tid] = e / bs;
            __syncthreads();
        }
        float acc[TAGS][3];
        #pragma unroll
        for (int s=0;s<TAGS;s++)
            #pragma unroll
            for (int j=0;j<3;j++) acc[s][j] = 0.f;
        const float* qb = q_emb + (size_t)qi*128*DD;
        for (int q=0;q<128;q++){
            float w0=arow[q], w1=arow[128+q], w2=arow[256+q], w3=arow[384+q], w4=arow[512+q];
            #pragma unroll
            for (int j=0;j<3;j++){
                float e = qb[q*DD + tid + j*256];
                acc[0][j]+=w0*e; acc[1][j]+=w1*e; acc[2][j]+=w2*e; acc[3][j]+=w3*e; acc[4][j]+=w4*e;
            }
        }
        #pragma unroll
        for (int j=0;j<3;j++){
            int d = tid + j*256;
            #pragma unroll
            for (int s=0;s<TAGS;s++){
                float m1 = ps[s*DD+d];
                float m2 = acc[s][j];
                float f[4] = { m1, m2, fabsf(m1-m2), m1*m2 };
                size_t base = ((size_t)(bq*TAGS + s))*FD;
                #pragma unroll
                for (int cchunk=0;cchunk<4;cchunk++){
                    float v = f[cchunk];
                    __nv_bfloat16 hh = __float2bfloat16(v);
                    g_FSh[base + cchunk*DD + d] = hh;
                    g_FSl[base + cchunk*DD + d] = __float2bfloat16(v - __bfloat162float(hh));
                }
            }
        }
        return;
    }
    // aprime: 800 blocks, (bq, q-quarter)
    int i = b - 200;
    int bq = i % 200, q0 = (i / 200)*32;
    float* ps  = sbuf;            // 3840
    float* sP  = sbuf + 3840;     // 640
    float* sqm = sbuf + 4480;     // 128
    int qi = bq / 5;
    int pi = (bq / 100)*5 + (bq % 5);
    for (int j=tid;j<TAGS*DD;j+=256) ps[j] = g_proto[(size_t)pi*TAGS*DD + j];
    for (int j=tid;j<640;j+=256) sP[j] = g_P[(size_t)bq*640 + j];
    if (tid < 128) sqm[tid] = q_mask[qi*128 + tid];
    __syncthreads();
    for (int q = q0; q < q0 + 32; q++){
        float p0=sP[q*5+0], p1=sP[q*5+1], p2=sP[q*5+2], p3=sP[q*5+3], p4=sP[q*5+4];
        float qm = sqm[q];
        const float* qr = q_emb + ((size_t)qi*128 + q)*DD;
        size_t base = ((size_t)bq*128 + q)*1536;
        for (int d = tid; d < DD; d += 256){
            float m2 = qm * (p0*ps[d] + p1*ps[DD+d] + p2*ps[2*DD+d] + p3*ps[3*DD+d] + p4*ps[4*DD+d]);
            float m1 = qr[d];
            float va = fabsf(m1 - m2);
            float vp = m1*m2;
            __nv_bfloat16 ah = __float2bfloat16(va);
            __nv_bfloat16 al = __float2bfloat16(va - __bfloat162float(ah));
            __nv_bfloat16 ph = __float2bfloat16(vp);
            __nv_bfloat16 pl = __float2bfloat16(vp - __bfloat162float(ph));
            g_Ahi[base + d]      = ah;  g_Alo[base + d]      = al;
            g_Ahi[base + DD + d] = ph;  g_Alo[base + DD + d] = pl;
        }
    }
}

// fused big: big_mma(1200) | es hgemm(48)
__global__ void __launch_bounds__(256,2) k_big(const float* __restrict__ q_mask,
                                               const float* __restrict__ proj_b)
{
    extern __shared__ __align__(128) char ds[];
    int b = blockIdx.x;
    if (b < 1200){ dev_big(b % 6, b / 6, q_mask, proj_b, ds); return; }
    int i = b - 1200;
    dev_hgemm<3072,1000,true>(i % 6, i / 6, g_FSh, g_FSl, g_Wh, g_Wl, g_es, proj_b, ds);
}

// ---------------- cat assembly -> bf16 hi/lo ----------------
__global__ void cat_kernel(const float* __restrict__ q_mask)
{
    int bq = blockIdx.x, tid = threadIdx.x;
    int qi = bq / 5;
    __shared__ float sc[8];
    __shared__ float qs_s;
    float v = (tid < 128) ? q_mask[qi*128 + tid] : 0.f;
    float ws = warpSum(v);
    if ((tid&31)==0) sc[tid>>5] = ws;
    __syncthreads();
    if (tid == 0){
        float q = 0.f;
        #pragma unroll
        for (int r=0;r<8;r++) q += sc[r];
        qs_s = q;
    }
    __syncthreads();
    float qs = qs_s;
    #pragma unroll
    for (int j=0;j<3;j++){
        int d = tid + j*256;
        float mx = 0.f, sm = 0.f;
        #pragma unroll
        for (int s=0;s<TAGS;s++){
            float e = g_es[((size_t)(bq*TAGS + s))*DD + d];
            mx = fmaxf(mx, e); sm += e;
        }
        float f[4] = { g_eqmax[(size_t)bq*DD + d],
                       g_eqsum[(size_t)bq*DD + d] / qs,
                       mx, sm * 0.2f };
        size_t b = (size_t)bq*FD;
        #pragma unroll
        for (int cchunk=0;cchunk<4;cchunk++){
            float val = f[cchunk];
            __nv_bfloat16 hh = __float2bfloat16(val);
            g_Ch[b + cchunk*DD + d] = hh;
            g_Cl[b + cchunk*DD + d] = __float2bfloat16(val - __bfloat162float(hh));
        }
    }
}

// ---------------- h = relu(cat @ rel_w1^T + b1) ----------------
__global__ void __launch_bounds__(256,2) k_h(const float* __restrict__ rel_b1)
{
    extern __shared__ __align__(128) char ds[];
    dev_hgemm<3072,200,true>(blockIdx.x, blockIdx.y, g_Ch, g_Cl, g_RWh, g_RWl, g_h, rel_b1, ds);
}

// ---------------- final logits ----------------
__global__ void logits_kernel(const float* __restrict__ rel_w2,
                              const float* __restrict__ rel_b2,
                              float* __restrict__ out)
{
    int g = blockIdx.x*8 + (threadIdx.x >> 5);
    if (g >= BQC) return;
    int lane = threadIdx.x & 31;
    float s = 0.f;
    for (int d=lane; d<DD; d+=32) s += rel_w2[d]*g_h[(size_t)g*DD + d];
    s = warpSum(s);
    if (!lane) out[g] = s + rel_b2[0];
}

// ---------------- launcher ----------------
extern "C" void kernel_launch(void* const* d_in, const int* in_sizes, int n_in,
                              void* d_out, int out_size)
{
    const float* s_emb   = (const float*)d_in[0];
    const float* q_emb   = (const float*)d_in[1];
    const float* s_mask  = (const float*)d_in[2];
    const float* q_mask  = (const float*)d_in[3];
    const float* s_label = (const float*)d_in[4];
    const float* proj_w  = (const float*)d_in[5];
    const float* proj_b  = (const float*)d_in[6];
    const float* rel_w1  = (const float*)d_in[7];
    const float* rel_b1  = (const float*)d_in[8];
    const float* rel_w2  = (const float*)d_in[9];
    const float* rel_b2  = (const float*)d_in[10];
    float* out = (float*)d_out;

    static bool attr_set = false;
    if (!attr_set){
        cudaFuncSetAttribute(k_big, cudaFuncAttributeMaxDynamicSharedMemorySize, DSMEM);
        cudaFuncSetAttribute(k_h,   cudaFuncAttributeMaxDynamicSharedMemorySize, DSMEM);
        cudaFuncSetAttribute(k_att_pw2_t1, cudaFuncAttributeMaxDynamicSharedMemorySize, DSMEM);
        attr_set = true;
    }

    k_prep          <<<50 + 2*9216 + 15360, 256>>>(s_emb, s_mask, s_label, proj_w, rel_w1, q_emb);
    proto_avg_kernel<<<150, 256>>>();
    k_att_pw2_t1    <<<BNQ + 12 + 240, 256, DSMEM>>>(q_emb, q_mask, proj_w + DD);
    k_light         <<<1000, 256>>>(q_emb, q_mask);
    k_big           <<<1248, 256, DSMEM>>>(q_mask, proj_b);
    cat_kernel      <<<BQC, 256>>>(q_mask);
    k_h             <<<dim3(6,2), 256, DSMEM>>>(rel_b1);
    logits_kernel   <<<25, 256>>>(rel_w2, rel_b2, out);
}